// round 1
// baseline (speedup 1.0000x reference)
#include <cuda_runtime.h>

// Problem constants
#define S_LEN 2048
#define HID   2048
#define NH    16
#define HD    128
#define BATCH 2
#define MROWS (BATCH * S_LEN)   // 4096

// Scratch (device globals -- allocation-free per harness rules)
__device__ float g_Q[BATCH * NH * S_LEN * HD];     // [b,h,s,d]  33.5 MB
__device__ float g_K[BATCH * NH * S_LEN * HD];
__device__ float g_V[BATCH * NH * S_LEN * HD];
__device__ float g_Ctx[MROWS * HID];               // [b,s,h*d]  33.5 MB
__device__ float g_P[134217728];                   // [bh, q, k] 512 MB scores/probs

// ---------------------------------------------------------------------------
// Shared 128x128x8 SGEMM microkernel step: acc += As_tile^T-ish outer products
// As[kk][r] = A[rowBase+r, k0+kk], Bs[kk][c] = B'[colBase+c, k0+kk]
// ---------------------------------------------------------------------------
__device__ __forceinline__ void mm_step(const float (*As)[128], const float (*Bs)[128],
                                        int tr, int tc, float acc[8][8])
{
#pragma unroll
    for (int kk = 0; kk < 8; kk++) {
        float4 a0 = *(const float4*)&As[kk][tr * 8];
        float4 a1 = *(const float4*)&As[kk][tr * 8 + 4];
        float4 b0 = *(const float4*)&Bs[kk][tc * 8];
        float4 b1 = *(const float4*)&Bs[kk][tc * 8 + 4];
        float ra[8] = {a0.x, a0.y, a0.z, a0.w, a1.x, a1.y, a1.z, a1.w};
        float rb[8] = {b0.x, b0.y, b0.z, b0.w, b1.x, b1.y, b1.z, b1.w};
#pragma unroll
        for (int i = 0; i < 8; i++)
#pragma unroll
            for (int j = 0; j < 8; j++)
                acc[i][j] = fmaf(ra[i], rb[j], acc[i][j]);
    }
}

// ---------------------------------------------------------------------------
// 1) QKV projection: C[m,n] = sum_k X[m,k] * W[n,k]  (W row-major [N,K] = W^T op)
//    blockIdx.z selects Wq/Wk/Wv; output written in [b,h,s,d] head-major layout
// ---------------------------------------------------------------------------
__global__ __launch_bounds__(256) void proj_kernel(
    const float* __restrict__ X,
    const float* __restrict__ Wq, const float* __restrict__ Wk,
    const float* __restrict__ Wv)
{
    const int K = HID;
    const float* W = (blockIdx.z == 0) ? Wq : (blockIdx.z == 1) ? Wk : Wv;
    float* Out     = (blockIdx.z == 0) ? g_Q : (blockIdx.z == 1) ? g_K : g_V;

    __shared__ __align__(16) float As[8][128];
    __shared__ __align__(16) float Bs[8][128];

    int tid = threadIdx.x;
    int rowBase = blockIdx.y * 128;
    int colBase = blockIdx.x * 128;
    int lr = tid >> 1;
    int lk = (tid & 1) << 2;
    const float* Aptr = X + (size_t)(rowBase + lr) * K + lk;
    const float* Bptr = W + (size_t)(colBase + lr) * K + lk;
    int tr = tid >> 4;
    int tc = tid & 15;

    float acc[8][8];
#pragma unroll
    for (int i = 0; i < 8; i++)
#pragma unroll
        for (int j = 0; j < 8; j++) acc[i][j] = 0.0f;

    for (int k0 = 0; k0 < K; k0 += 8) {
        float4 a4 = *(const float4*)(Aptr + k0);
        float4 b4 = *(const float4*)(Bptr + k0);
        As[lk + 0][lr] = a4.x; As[lk + 1][lr] = a4.y;
        As[lk + 2][lr] = a4.z; As[lk + 3][lr] = a4.w;
        Bs[lk + 0][lr] = b4.x; Bs[lk + 1][lr] = b4.y;
        Bs[lk + 2][lr] = b4.z; Bs[lk + 3][lr] = b4.w;
        __syncthreads();
        mm_step(As, Bs, tr, tc, acc);
        __syncthreads();
    }

    // head-major epilogue: (b, h, s, d)
    int h = colBase >> 7;   // tile width 128 == head width, aligned
#pragma unroll
    for (int i = 0; i < 8; i++) {
        int m = rowBase + tr * 8 + i;
        int b = m >> 11, s = m & 2047;
        float* orow = Out + (((size_t)(b * NH + h) * S_LEN + s) << 7);
#pragma unroll
        for (int j = 0; j < 8; j++) {
            int d = (colBase & 127) + tc * 8 + j;   // == tc*8+j
            orow[d] = acc[i][j];
        }
    }
}

// ---------------------------------------------------------------------------
// 2) RoPE on Q and K in place. thread handles pair (i, i+64) of one row.
//    positions are arange(S) per batch (matches reference setup).
// ---------------------------------------------------------------------------
__global__ void rope_kernel()
{
    const int half = BATCH * NH * S_LEN * 64;   // 4194304
    int idx = blockIdx.x * blockDim.x + threadIdx.x;
    if (idx >= 2 * half) return;
    float* buf = (idx < half) ? g_Q : g_K;
    int r = (idx < half) ? idx : idx - half;
    int i = r & 63;
    int row = r >> 6;              // [0, B*NH*S)
    int s = row & 2047;            // position
    float fp = (float)s;
    float invf = (float)(1.0 / pow(10000.0, (double)(2 * i) / 128.0));
    float ang = fp * invf;
    float c, sn;
    c = cosf(ang);
    sn = sinf(ang);
    float* base = buf + ((size_t)row << 7);
    float x1 = base[i];
    float x2 = base[i + 64];
    base[i]      = x1 * c - x2 * sn;
    base[i + 64] = x2 * c + x1 * sn;
}

// ---------------------------------------------------------------------------
// 3) Scores: S[q,k] = scale * dot(Q[q], K[k]) per head, causal tiles only
// ---------------------------------------------------------------------------
__global__ __launch_bounds__(256) void scores_kernel()
{
    int z = blockIdx.z;                  // bh in [0,32)
    int rowBase = blockIdx.y * 128;      // q
    int colBase = blockIdx.x * 128;      // k
    if (colBase > rowBase) return;       // fully masked tile: never read

    const float* A = g_Q + (size_t)z * S_LEN * HD;
    const float* B = g_K + (size_t)z * S_LEN * HD;
    float* C = g_P + (size_t)z * S_LEN * S_LEN;

    __shared__ __align__(16) float As[8][128];
    __shared__ __align__(16) float Bs[8][128];

    int tid = threadIdx.x;
    int lr = tid >> 1;
    int lk = (tid & 1) << 2;
    const float* Aptr = A + (size_t)(rowBase + lr) * HD + lk;
    const float* Bptr = B + (size_t)(colBase + lr) * HD + lk;
    int tr = tid >> 4;
    int tc = tid & 15;

    float acc[8][8];
#pragma unroll
    for (int i = 0; i < 8; i++)
#pragma unroll
        for (int j = 0; j < 8; j++) acc[i][j] = 0.0f;

    for (int k0 = 0; k0 < HD; k0 += 8) {
        float4 a4 = *(const float4*)(Aptr + k0);
        float4 b4 = *(const float4*)(Bptr + k0);
        As[lk + 0][lr] = a4.x; As[lk + 1][lr] = a4.y;
        As[lk + 2][lr] = a4.z; As[lk + 3][lr] = a4.w;
        Bs[lk + 0][lr] = b4.x; Bs[lk + 1][lr] = b4.y;
        Bs[lk + 2][lr] = b4.z; Bs[lk + 3][lr] = b4.w;
        __syncthreads();
        mm_step(As, Bs, tr, tc, acc);
        __syncthreads();
    }

    const float scale = 0.08838834764831845f;   // 1/sqrt(128)
#pragma unroll
    for (int i = 0; i < 8; i++) {
        int m = rowBase + tr * 8 + i;
#pragma unroll
        for (int j = 0; j < 8; j++) {
            int n = colBase + tc * 8 + j;
            C[(size_t)m * S_LEN + n] = (n <= m) ? acc[i][j] * scale : -1e30f;
        }
    }
}

// ---------------------------------------------------------------------------
// 4) Causal row softmax in place; writes 0 for k > q
// ---------------------------------------------------------------------------
__global__ __launch_bounds__(256) void softmax_kernel()
{
    int q = blockIdx.x;
    int z = blockIdx.y;
    float* row = g_P + (size_t)z * S_LEN * S_LEN + (size_t)q * S_LEN;
    int len = q + 1;
    int tid = threadIdx.x;
    __shared__ float red[256];

    float m = -3.4e38f;
    for (int i = tid; i < len; i += 256) m = fmaxf(m, row[i]);
    red[tid] = m;
    __syncthreads();
    for (int s = 128; s > 0; s >>= 1) {
        if (tid < s) red[tid] = fmaxf(red[tid], red[tid + s]);
        __syncthreads();
    }
    m = red[0];
    __syncthreads();

    float sum = 0.0f;
    for (int i = tid; i < len; i += 256) sum += expf(row[i] - m);
    red[tid] = sum;
    __syncthreads();
    for (int s = 128; s > 0; s >>= 1) {
        if (tid < s) red[tid] += red[tid + s];
        __syncthreads();
    }
    float inv = 1.0f / red[0];

    for (int i = tid; i < S_LEN; i += 256)
        row[i] = (i < len) ? expf(row[i] - m) * inv : 0.0f;
}

// ---------------------------------------------------------------------------
// 5) PV: O[q,d] = sum_k P[q,k] V[k,d] per head; k loop clipped by causality.
//    Writes straight into context layout [b, s, h*128+d].
// ---------------------------------------------------------------------------
__global__ __launch_bounds__(256) void pv_kernel()
{
    int z = blockIdx.y;                  // bh
    int b = z >> 4, h = z & 15;
    int rowBase = blockIdx.x * 128;      // q tile
    const float* A  = g_P + (size_t)z * S_LEN * S_LEN;
    const float* Bv = g_V + (size_t)z * S_LEN * HD;

    __shared__ __align__(16) float As[8][128];
    __shared__ __align__(16) float Bs[8][128];

    int tid = threadIdx.x;
    int lr = tid >> 1;
    int lk = (tid & 1) << 2;
    int bkr = tid >> 5;
    int bnc = (tid & 31) << 2;
    int tr = tid >> 4;
    int tc = tid & 15;

    float acc[8][8];
#pragma unroll
    for (int i = 0; i < 8; i++)
#pragma unroll
        for (int j = 0; j < 8; j++) acc[i][j] = 0.0f;

    int kmax = rowBase + 128;            // P[q,k]=0 for k>q; max q in tile = rowBase+127
    for (int k0 = 0; k0 < kmax; k0 += 8) {
        float4 a4 = *(const float4*)(A + (size_t)(rowBase + lr) * S_LEN + k0 + lk);
        As[lk + 0][lr] = a4.x; As[lk + 1][lr] = a4.y;
        As[lk + 2][lr] = a4.z; As[lk + 3][lr] = a4.w;
        float4 b4 = *(const float4*)(Bv + (size_t)(k0 + bkr) * HD + bnc);
        *(float4*)&Bs[bkr][bnc] = b4;
        __syncthreads();
        mm_step(As, Bs, tr, tc, acc);
        __syncthreads();
    }

#pragma unroll
    for (int i = 0; i < 8; i++) {
        int q = rowBase + tr * 8 + i;
        float* crow = g_Ctx + (size_t)(b * S_LEN + q) * HID + h * HD;
#pragma unroll
        for (int j = 0; j < 8; j++) {
            int d = tc * 8 + j;
            crow[d] = acc[i][j];
        }
    }
}

// ---------------------------------------------------------------------------
// 6) Output projection: out[m,n] = sum_k Ctx[m,k] * Wo[n,k]
// ---------------------------------------------------------------------------
__global__ __launch_bounds__(256) void out_proj_kernel(const float* __restrict__ Wo,
                                                       float* __restrict__ out)
{
    const int K = HID;
    __shared__ __align__(16) float As[8][128];
    __shared__ __align__(16) float Bs[8][128];

    int tid = threadIdx.x;
    int rowBase = blockIdx.y * 128;
    int colBase = blockIdx.x * 128;
    int lr = tid >> 1;
    int lk = (tid & 1) << 2;
    const float* Aptr = g_Ctx + (size_t)(rowBase + lr) * K + lk;
    const float* Bptr = Wo + (size_t)(colBase + lr) * K + lk;
    int tr = tid >> 4;
    int tc = tid & 15;

    float acc[8][8];
#pragma unroll
    for (int i = 0; i < 8; i++)
#pragma unroll
        for (int j = 0; j < 8; j++) acc[i][j] = 0.0f;

    for (int k0 = 0; k0 < K; k0 += 8) {
        float4 a4 = *(const float4*)(Aptr + k0);
        float4 b4 = *(const float4*)(Bptr + k0);
        As[lk + 0][lr] = a4.x; As[lk + 1][lr] = a4.y;
        As[lk + 2][lr] = a4.z; As[lk + 3][lr] = a4.w;
        Bs[lk + 0][lr] = b4.x; Bs[lk + 1][lr] = b4.y;
        Bs[lk + 2][lr] = b4.z; Bs[lk + 3][lr] = b4.w;
        __syncthreads();
        mm_step(As, Bs, tr, tc, acc);
        __syncthreads();
    }

#pragma unroll
    for (int i = 0; i < 8; i++) {
        int m = rowBase + tr * 8 + i;
#pragma unroll
        for (int j = 0; j < 8; j++) {
            int n = colBase + tc * 8 + j;
            out[(size_t)m * HID + n] = acc[i][j];
        }
    }
}

// ---------------------------------------------------------------------------
extern "C" void kernel_launch(void* const* d_in, const int* in_sizes, int n_in,
                              void* d_out, int out_size)
{
    (void)in_sizes; (void)n_in; (void)out_size;
    const float* X  = (const float*)d_in[0];
    // d_in[1] = attention_mask (causal; applied analytically)
    // d_in[2] = position_ids   (arange(S); derived from s directly)
    const float* Wq = (const float*)d_in[3];
    const float* Wk = (const float*)d_in[4];
    const float* Wv = (const float*)d_in[5];
    const float* Wo = (const float*)d_in[6];
    float* out = (float*)d_out;

    proj_kernel<<<dim3(16, 32, 3), 256>>>(X, Wq, Wk, Wv);
    rope_kernel<<<32768, 256>>>();
    scores_kernel<<<dim3(16, 16, 32), 256>>>();
    softmax_kernel<<<dim3(2048, 32), 256>>>();
    pv_kernel<<<dim3(16, 32), 256>>>();
    out_proj_kernel<<<dim3(16, 32), 256>>>(Wo, out);
}

// round 2
// speedup vs baseline: 1.0041x; 1.0041x over previous
#include <cuda_runtime.h>

// Problem constants
#define S_LEN 2048
#define HID   2048
#define NH    16
#define HD    128
#define BATCH 2
#define MROWS (BATCH * S_LEN)   // 4096

// Scratch (device globals -- allocation-free per harness rules)
__device__ float g_Q[BATCH * NH * S_LEN * HD];     // [b,h,s,d]  33.5 MB
__device__ float g_K[BATCH * NH * S_LEN * HD];
__device__ float g_V[BATCH * NH * S_LEN * HD];
__device__ float g_Ctx[MROWS * HID];               // [b,s,h*d]  33.5 MB
__device__ float g_P[134217728];                   // [bh, q, k] 512 MB scores/probs

// ---------------------------------------------------------------------------
// Shared 128x128x8 SGEMM microkernel step: acc += As_tile^T-ish outer products
// As[kk][r] = A[rowBase+r, k0+kk], Bs[kk][c] = B'[colBase+c, k0+kk]
// ---------------------------------------------------------------------------
__device__ __forceinline__ void mm_step(const float (*As)[128], const float (*Bs)[128],
                                        int tr, int tc, float acc[8][8])
{
#pragma unroll
    for (int kk = 0; kk < 8; kk++) {
        float4 a0 = *(const float4*)&As[kk][tr * 8];
        float4 a1 = *(const float4*)&As[kk][tr * 8 + 4];
        float4 b0 = *(const float4*)&Bs[kk][tc * 8];
        float4 b1 = *(const float4*)&Bs[kk][tc * 8 + 4];
        float ra[8] = {a0.x, a0.y, a0.z, a0.w, a1.x, a1.y, a1.z, a1.w};
        float rb[8] = {b0.x, b0.y, b0.z, b0.w, b1.x, b1.y, b1.z, b1.w};
#pragma unroll
        for (int i = 0; i < 8; i++)
#pragma unroll
            for (int j = 0; j < 8; j++)
                acc[i][j] = fmaf(ra[i], rb[j], acc[i][j]);
    }
}

// ---------------------------------------------------------------------------
// 1) QKV projection: C[m,n] = sum_k X[m,k] * W[n,k]  (W row-major [N,K] = W^T op)
//    blockIdx.z selects Wq/Wk/Wv; output written in [b,h,s,d] head-major layout
// ---------------------------------------------------------------------------
__global__ __launch_bounds__(256) void proj_kernel(
    const float* __restrict__ X,
    const float* __restrict__ Wq, const float* __restrict__ Wk,
    const float* __restrict__ Wv)
{
    const int K = HID;
    const float* W = (blockIdx.z == 0) ? Wq : (blockIdx.z == 1) ? Wk : Wv;
    float* Out     = (blockIdx.z == 0) ? g_Q : (blockIdx.z == 1) ? g_K : g_V;

    __shared__ __align__(16) float As[8][128];
    __shared__ __align__(16) float Bs[8][128];

    int tid = threadIdx.x;
    int rowBase = blockIdx.y * 128;
    int colBase = blockIdx.x * 128;
    int lr = tid >> 1;
    int lk = (tid & 1) << 2;
    const float* Aptr = X + (size_t)(rowBase + lr) * K + lk;
    const float* Bptr = W + (size_t)(colBase + lr) * K + lk;
    int tr = tid >> 4;
    int tc = tid & 15;

    float acc[8][8];
#pragma unroll
    for (int i = 0; i < 8; i++)
#pragma unroll
        for (int j = 0; j < 8; j++) acc[i][j] = 0.0f;

    for (int k0 = 0; k0 < K; k0 += 8) {
        float4 a4 = *(const float4*)(Aptr + k0);
        float4 b4 = *(const float4*)(Bptr + k0);
        As[lk + 0][lr] = a4.x; As[lk + 1][lr] = a4.y;
        As[lk + 2][lr] = a4.z; As[lk + 3][lr] = a4.w;
        Bs[lk + 0][lr] = b4.x; Bs[lk + 1][lr] = b4.y;
        Bs[lk + 2][lr] = b4.z; Bs[lk + 3][lr] = b4.w;
        __syncthreads();
        mm_step(As, Bs, tr, tc, acc);
        __syncthreads();
    }

    // head-major epilogue: (b, h, s, d)
    int h = colBase >> 7;   // tile width 128 == head width, aligned
#pragma unroll
    for (int i = 0; i < 8; i++) {
        int m = rowBase + tr * 8 + i;
        int b = m >> 11, s = m & 2047;
        float* orow = Out + (((size_t)(b * NH + h) * S_LEN + s) << 7);
#pragma unroll
        for (int j = 0; j < 8; j++) {
            int d = (colBase & 127) + tc * 8 + j;   // == tc*8+j
            orow[d] = acc[i][j];
        }
    }
}

// ---------------------------------------------------------------------------
// 2) RoPE on Q and K in place. thread handles pair (i, i+64) of one row.
//    positions are arange(S) per batch (matches reference setup).
// ---------------------------------------------------------------------------
__global__ void rope_kernel()
{
    const int half = BATCH * NH * S_LEN * 64;   // 4194304
    int idx = blockIdx.x * blockDim.x + threadIdx.x;
    if (idx >= 2 * half) return;
    float* buf = (idx < half) ? g_Q : g_K;
    int r = (idx < half) ? idx : idx - half;
    int i = r & 63;
    int row = r >> 6;              // [0, B*NH*S)
    int s = row & 2047;            // position
    float fp = (float)s;
    float invf = (float)(1.0 / pow(10000.0, (double)(2 * i) / 128.0));
    float ang = fp * invf;
    float c, sn;
    c = cosf(ang);
    sn = sinf(ang);
    float* base = buf + ((size_t)row << 7);
    float x1 = base[i];
    float x2 = base[i + 64];
    base[i]      = x1 * c - x2 * sn;
    base[i + 64] = x2 * c + x1 * sn;
}

// ---------------------------------------------------------------------------
// 3) Scores: S[q,k] = scale * dot(Q[q], K[k]) per head, causal tiles only
// ---------------------------------------------------------------------------
__global__ __launch_bounds__(256) void scores_kernel()
{
    int z = blockIdx.z;                  // bh in [0,32)
    int rowBase = blockIdx.y * 128;      // q
    int colBase = blockIdx.x * 128;      // k
    if (colBase > rowBase) return;       // fully masked tile: never read

    const float* A = g_Q + (size_t)z * S_LEN * HD;
    const float* B = g_K + (size_t)z * S_LEN * HD;
    float* C = g_P + (size_t)z * S_LEN * S_LEN;

    __shared__ __align__(16) float As[8][128];
    __shared__ __align__(16) float Bs[8][128];

    int tid = threadIdx.x;
    int lr = tid >> 1;
    int lk = (tid & 1) << 2;
    const float* Aptr = A + (size_t)(rowBase + lr) * HD + lk;
    const float* Bptr = B + (size_t)(colBase + lr) * HD + lk;
    int tr = tid >> 4;
    int tc = tid & 15;

    float acc[8][8];
#pragma unroll
    for (int i = 0; i < 8; i++)
#pragma unroll
        for (int j = 0; j < 8; j++) acc[i][j] = 0.0f;

    for (int k0 = 0; k0 < HD; k0 += 8) {
        float4 a4 = *(const float4*)(Aptr + k0);
        float4 b4 = *(const float4*)(Bptr + k0);
        As[lk + 0][lr] = a4.x; As[lk + 1][lr] = a4.y;
        As[lk + 2][lr] = a4.z; As[lk + 3][lr] = a4.w;
        Bs[lk + 0][lr] = b4.x; Bs[lk + 1][lr] = b4.y;
        Bs[lk + 2][lr] = b4.z; Bs[lk + 3][lr] = b4.w;
        __syncthreads();
        mm_step(As, Bs, tr, tc, acc);
        __syncthreads();
    }

    const float scale = 0.08838834764831845f;   // 1/sqrt(128)
#pragma unroll
    for (int i = 0; i < 8; i++) {
        int m = rowBase + tr * 8 + i;
#pragma unroll
        for (int j = 0; j < 8; j++) {
            int n = colBase + tc * 8 + j;
            C[(size_t)m * S_LEN + n] = (n <= m) ? acc[i][j] * scale : -1e30f;
        }
    }
}

// ---------------------------------------------------------------------------
// 4) Causal row softmax in place; writes 0 for k > q
// ---------------------------------------------------------------------------
__global__ __launch_bounds__(256) void softmax_kernel()
{
    int q = blockIdx.x;
    int z = blockIdx.y;
    float* row = g_P + (size_t)z * S_LEN * S_LEN + (size_t)q * S_LEN;
    int len = q + 1;
    int tid = threadIdx.x;
    __shared__ float red[256];

    float m = -3.4e38f;
    for (int i = tid; i < len; i += 256) m = fmaxf(m, row[i]);
    red[tid] = m;
    __syncthreads();
    for (int s = 128; s > 0; s >>= 1) {
        if (tid < s) red[tid] = fmaxf(red[tid], red[tid + s]);
        __syncthreads();
    }
    m = red[0];
    __syncthreads();

    float sum = 0.0f;
    for (int i = tid; i < len; i += 256) sum += expf(row[i] - m);
    red[tid] = sum;
    __syncthreads();
    for (int s = 128; s > 0; s >>= 1) {
        if (tid < s) red[tid] += red[tid + s];
        __syncthreads();
    }
    float inv = 1.0f / red[0];

    for (int i = tid; i < S_LEN; i += 256)
        row[i] = (i < len) ? expf(row[i] - m) * inv : 0.0f;
}

// ---------------------------------------------------------------------------
// 5) PV: O[q,d] = sum_k P[q,k] V[k,d] per head; k loop clipped by causality.
//    Writes straight into context layout [b, s, h*128+d].
// ---------------------------------------------------------------------------
__global__ __launch_bounds__(256) void pv_kernel()
{
    int z = blockIdx.y;                  // bh
    int b = z >> 4, h = z & 15;
    int rowBase = blockIdx.x * 128;      // q tile
    const float* A  = g_P + (size_t)z * S_LEN * S_LEN;
    const float* Bv = g_V + (size_t)z * S_LEN * HD;

    __shared__ __align__(16) float As[8][128];
    __shared__ __align__(16) float Bs[8][128];

    int tid = threadIdx.x;
    int lr = tid >> 1;
    int lk = (tid & 1) << 2;
    int bkr = tid >> 5;
    int bnc = (tid & 31) << 2;
    int tr = tid >> 4;
    int tc = tid & 15;

    float acc[8][8];
#pragma unroll
    for (int i = 0; i < 8; i++)
#pragma unroll
        for (int j = 0; j < 8; j++) acc[i][j] = 0.0f;

    int kmax = rowBase + 128;            // P[q,k]=0 for k>q; max q in tile = rowBase+127
    for (int k0 = 0; k0 < kmax; k0 += 8) {
        float4 a4 = *(const float4*)(A + (size_t)(rowBase + lr) * S_LEN + k0 + lk);
        As[lk + 0][lr] = a4.x; As[lk + 1][lr] = a4.y;
        As[lk + 2][lr] = a4.z; As[lk + 3][lr] = a4.w;
        float4 b4 = *(const float4*)(Bv + (size_t)(k0 + bkr) * HD + bnc);
        *(float4*)&Bs[bkr][bnc] = b4;
        __syncthreads();
        mm_step(As, Bs, tr, tc, acc);
        __syncthreads();
    }

#pragma unroll
    for (int i = 0; i < 8; i++) {
        int q = rowBase + tr * 8 + i;
        float* crow = g_Ctx + (size_t)(b * S_LEN + q) * HID + h * HD;
#pragma unroll
        for (int j = 0; j < 8; j++) {
            int d = tc * 8 + j;
            crow[d] = acc[i][j];
        }
    }
}

// ---------------------------------------------------------------------------
// 6) Output projection: out[m,n] = sum_k Ctx[m,k] * Wo[n,k]
// ---------------------------------------------------------------------------
__global__ __launch_bounds__(256) void out_proj_kernel(const float* __restrict__ Wo,
                                                       float* __restrict__ out)
{
    const int K = HID;
    __shared__ __align__(16) float As[8][128];
    __shared__ __align__(16) float Bs[8][128];

    int tid = threadIdx.x;
    int rowBase = blockIdx.y * 128;
    int colBase = blockIdx.x * 128;
    int lr = tid >> 1;
    int lk = (tid & 1) << 2;
    const float* Aptr = g_Ctx + (size_t)(rowBase + lr) * K + lk;
    const float* Bptr = Wo + (size_t)(colBase + lr) * K + lk;
    int tr = tid >> 4;
    int tc = tid & 15;

    float acc[8][8];
#pragma unroll
    for (int i = 0; i < 8; i++)
#pragma unroll
        for (int j = 0; j < 8; j++) acc[i][j] = 0.0f;

    for (int k0 = 0; k0 < K; k0 += 8) {
        float4 a4 = *(const float4*)(Aptr + k0);
        float4 b4 = *(const float4*)(Bptr + k0);
        As[lk + 0][lr] = a4.x; As[lk + 1][lr] = a4.y;
        As[lk + 2][lr] = a4.z; As[lk + 3][lr] = a4.w;
        Bs[lk + 0][lr] = b4.x; Bs[lk + 1][lr] = b4.y;
        Bs[lk + 2][lr] = b4.z; Bs[lk + 3][lr] = b4.w;
        __syncthreads();
        mm_step(As, Bs, tr, tc, acc);
        __syncthreads();
    }

#pragma unroll
    for (int i = 0; i < 8; i++) {
        int m = rowBase + tr * 8 + i;
#pragma unroll
        for (int j = 0; j < 8; j++) {
            int n = colBase + tc * 8 + j;
            out[(size_t)m * HID + n] = acc[i][j];
        }
    }
}

// ---------------------------------------------------------------------------
extern "C" void kernel_launch(void* const* d_in, const int* in_sizes, int n_in,
                              void* d_out, int out_size)
{
    (void)in_sizes; (void)n_in; (void)out_size;
    const float* X  = (const float*)d_in[0];
    // d_in[1] = attention_mask (causal; applied analytically)
    // d_in[2] = position_ids   (arange(S); derived from s directly)
    const float* Wq = (const float*)d_in[3];
    const float* Wk = (const float*)d_in[4];
    const float* Wv = (const float*)d_in[5];
    const float* Wo = (const float*)d_in[6];
    float* out = (float*)d_out;

    proj_kernel<<<dim3(16, 32, 3), 256>>>(X, Wq, Wk, Wv);
    rope_kernel<<<32768, 256>>>();
    scores_kernel<<<dim3(16, 16, 32), 256>>>();
    softmax_kernel<<<dim3(2048, 32), 256>>>();
    pv_kernel<<<dim3(16, 32), 256>>>();
    out_proj_kernel<<<dim3(16, 32), 256>>>(Wo, out);
}

// round 4
// speedup vs baseline: 1.9508x; 1.9428x over previous
#include <cuda_runtime.h>
#include <cuda_bf16.h>
#include <stdint.h>
#include <math.h>

#define S_LEN 2048
#define HID   2048
#define NH    16
#define HD    128
#define BATCH 2
#define MROWS 4096
#define NBH   32
#define TILE_B   16384            // 128 rows x 128 bytes (64 bf16 of K)
#define STAGE_B  (4 * TILE_B)     // Ahi, Alo, Bhi, Blo
#define SMEM_DYN (2 * STAGE_B)    // 2 stages = 128 KB

// ---------------- scratch globals ------------------------------------------
__device__ __align__(16) __nv_bfloat16 g_Xhi[MROWS * HID];
__device__ __align__(16) __nv_bfloat16 g_Xlo[MROWS * HID];
__device__ __align__(16) __nv_bfloat16 g_Whi[4][HID * HID];   // Wq,Wk,Wv,Wo
__device__ __align__(16) __nv_bfloat16 g_Wlo[4][HID * HID];
__device__ __align__(16) __nv_bfloat16 g_Qhi[NBH * S_LEN * HD];
__device__ __align__(16) __nv_bfloat16 g_Qlo[NBH * S_LEN * HD];
__device__ __align__(16) __nv_bfloat16 g_Khi[NBH * S_LEN * HD];
__device__ __align__(16) __nv_bfloat16 g_Klo[NBH * S_LEN * HD];
__device__ __align__(16) __nv_bfloat16 g_Vthi[NBH * HD * S_LEN];   // [bh,d,s]
__device__ __align__(16) __nv_bfloat16 g_Vtlo[NBH * HD * S_LEN];
__device__ __align__(16) __nv_bfloat16 g_Phi[(size_t)NBH * S_LEN * S_LEN];
__device__ __align__(16) __nv_bfloat16 g_Plo[(size_t)NBH * S_LEN * S_LEN];
__device__ __align__(16) __nv_bfloat16 g_Chi[MROWS * HID];
__device__ __align__(16) __nv_bfloat16 g_Clo[MROWS * HID];

// ---------------- helpers ---------------------------------------------------
__device__ __forceinline__ uint32_t smem_u32(const void* p) {
    uint32_t a;
    asm("{ .reg .u64 t; cvta.to.shared.u64 t, %1; cvt.u32.u64 %0, t; }"
        : "=r"(a) : "l"(p));
    return a;
}
#define SWZ(o) ((o) ^ (((o) >> 3) & 0x70))
#define CP16(dst, src) \
    asm volatile("cp.async.cg.shared.global [%0], [%1], 16;" \
                 :: "r"((uint32_t)(dst)), "l"(src) : "memory")

__device__ __forceinline__ void ldsm_x4(uint32_t r[4], uint32_t addr) {
    asm volatile("ldmatrix.sync.aligned.m8n8.x4.shared.b16 {%0,%1,%2,%3}, [%4];"
        : "=r"(r[0]), "=r"(r[1]), "=r"(r[2]), "=r"(r[3]) : "r"(addr));
}
__device__ __forceinline__ void ldsm_x2(uint32_t r[2], uint32_t addr) {
    asm volatile("ldmatrix.sync.aligned.m8n8.x2.shared.b16 {%0,%1}, [%2];"
        : "=r"(r[0]), "=r"(r[1]) : "r"(addr));
}
__device__ __forceinline__ void mma16816(float d[4], const uint32_t a[4],
                                         const uint32_t b[2]) {
    asm volatile("mma.sync.aligned.m16n8k16.row.col.f32.bf16.bf16.f32 "
        "{%0,%1,%2,%3}, {%4,%5,%6,%7}, {%8,%9}, {%0,%1,%2,%3};"
        : "+f"(d[0]), "+f"(d[1]), "+f"(d[2]), "+f"(d[3])
        : "r"(a[0]), "r"(a[1]), "r"(a[2]), "r"(a[3]), "r"(b[0]), "r"(b[1]));
}
__device__ __forceinline__ void split_st(float v, __nv_bfloat16* ph, __nv_bfloat16* pl) {
    __nv_bfloat16 h = __float2bfloat16_rn(v);
    *ph = h;
    *pl = __float2bfloat16_rn(v - __bfloat162float(h));
}

// ---------------- fp32 -> bf16 hi/lo conversion -----------------------------
__global__ void conv_kernel(const float* __restrict__ src, int which)
{
    int n = (which == 4) ? MROWS * HID : HID * HID;
    int i = blockIdx.x * 256 + threadIdx.x;
    if (i >= n) return;
    __nv_bfloat16 *dh, *dl;
    if (which == 4) { dh = g_Xhi; dl = g_Xlo; }
    else            { dh = g_Whi[which]; dl = g_Wlo[which]; }
    split_st(src[i], dh + i, dl + i);
}

// ---------------- RoPE on split Q/K in place ---------------------------------
__global__ void rope_kernel()
{
    const int half = NBH * S_LEN * 64;
    int idx = blockIdx.x * 256 + threadIdx.x;
    if (idx >= 2 * half) return;
    __nv_bfloat16 *bh, *bl;
    int r;
    if (idx < half) { bh = g_Qhi; bl = g_Qlo; r = idx; }
    else            { bh = g_Khi; bl = g_Klo; r = idx - half; }
    int i = r & 63;
    int row = r >> 6;
    int s = row & 2047;
    float invf = (float)(1.0 / pow(10000.0, (double)(2 * i) / 128.0));
    float ang = (float)s * invf;
    float c = cosf(ang), sn = sinf(ang);
    size_t base = (size_t)row * HD;
    float x1 = __bfloat162float(bh[base + i])      + __bfloat162float(bl[base + i]);
    float x2 = __bfloat162float(bh[base + i + 64]) + __bfloat162float(bl[base + i + 64]);
    split_st(x1 * c - x2 * sn, bh + base + i,      bl + base + i);
    split_st(x2 * c + x1 * sn, bh + base + i + 64, bl + base + i + 64);
}

// ---------------- causal softmax on split scores, in place ------------------
__global__ __launch_bounds__(256) void softmax_kernel()
{
    __shared__ float buf[S_LEN];
    __shared__ float red[256];
    int q = blockIdx.x, z = blockIdx.y, tid = threadIdx.x;
    size_t ro = (size_t)z * S_LEN * S_LEN + (size_t)q * S_LEN;
    int len = q + 1;
    int upper = ((q >> 7) + 1) << 7;

    float m = -3.4e38f;
    for (int i = tid; i < len; i += 256) {
        float v = __bfloat162float(g_Phi[ro + i]) + __bfloat162float(g_Plo[ro + i]);
        buf[i] = v;
        m = fmaxf(m, v);
    }
    red[tid] = m; __syncthreads();
    for (int s = 128; s > 0; s >>= 1) {
        if (tid < s) red[tid] = fmaxf(red[tid], red[tid + s]);
        __syncthreads();
    }
    m = red[0]; __syncthreads();

    float sum = 0.0f;
    for (int i = tid; i < len; i += 256) sum += expf(buf[i] - m);
    red[tid] = sum; __syncthreads();
    for (int s = 128; s > 0; s >>= 1) {
        if (tid < s) red[tid] += red[tid + s];
        __syncthreads();
    }
    float inv = 1.0f / red[0];

    for (int i = tid; i < upper; i += 256) {
        float p = (i < len) ? expf(buf[i] - m) * inv : 0.0f;
        split_st(p, g_Phi + ro + i, g_Plo + ro + i);
    }
}

// ---------------- generic split-bf16 mma.sync GEMM ---------------------------
// C[m,n] = sum_k (Ahi+Alo)[m,k]*(Bhi+Blo)[n,k], lo*lo dropped.
// 128x128 block tile, 8 warps of 32(M)x64(N), K chunks of 64, 2-stage cp.async.
// modes: 0=QKV proj  1=scores  2=PV  3=out proj
__global__ __launch_bounds__(256) void gemm_kernel(int mode, float* __restrict__ out)
{
    extern __shared__ char smem[];
    uint32_t sb = smem_u32(smem);

    int tid = threadIdx.x;
    int wid = tid >> 5, lane = tid & 31;
    int wm = wid & 3, wn = wid >> 2;
    int t = blockIdx.x;

    const __nv_bfloat16 *Ahi, *Alo, *Bhi, *Blo;
    int strideA, strideB, nChunks;
    int mtile = 0, ntile = 0, z = 0, qt = 0, kt = 0, w = 0;

    if (mode == 0) {
        w = t >> 9; int r = t & 511; mtile = r >> 4; ntile = r & 15;
        Ahi = g_Xhi + (size_t)mtile * 128 * HID;
        Alo = g_Xlo + (size_t)mtile * 128 * HID;
        Bhi = g_Whi[w] + (size_t)ntile * 128 * HID;
        Blo = g_Wlo[w] + (size_t)ntile * 128 * HID;
        strideA = HID; strideB = HID; nChunks = 32;
    } else if (mode == 1) {
        z = t / 136; int p = t % 136;
        qt = 0;
        while ((qt + 1) * (qt + 2) / 2 <= p) qt++;
        kt = p - qt * (qt + 1) / 2;
        Ahi = g_Qhi + ((size_t)z * S_LEN + qt * 128) * HD;
        Alo = g_Qlo + ((size_t)z * S_LEN + qt * 128) * HD;
        Bhi = g_Khi + ((size_t)z * S_LEN + kt * 128) * HD;
        Blo = g_Klo + ((size_t)z * S_LEN + kt * 128) * HD;
        strideA = HD; strideB = HD; nChunks = 2;
    } else if (mode == 2) {
        z = t >> 4; qt = t & 15;
        Ahi = g_Phi + (size_t)z * S_LEN * S_LEN + (size_t)qt * 128 * S_LEN;
        Alo = g_Plo + (size_t)z * S_LEN * S_LEN + (size_t)qt * 128 * S_LEN;
        Bhi = g_Vthi + (size_t)z * HD * S_LEN;
        Blo = g_Vtlo + (size_t)z * HD * S_LEN;
        strideA = S_LEN; strideB = S_LEN; nChunks = 2 * (qt + 1);
    } else {
        mtile = t >> 4; ntile = t & 15;
        Ahi = g_Chi + (size_t)mtile * 128 * HID;
        Alo = g_Clo + (size_t)mtile * 128 * HID;
        Bhi = g_Whi[3] + (size_t)ntile * 128 * HID;
        Blo = g_Wlo[3] + (size_t)ntile * 128 * HID;
        strideA = HID; strideB = HID; nChunks = 32;
    }

    // per-thread load slots: 16 cp.async of 16B each per stage
    int lrow[16], lseg[16], ltile[16];
    uint32_t ldst[16];
#pragma unroll
    for (int it = 0; it < 16; it++) {
        int u = tid + it * 256;
        int tile = u >> 10;
        int v = u & 1023;
        int row = v >> 3, seg = v & 7;
        ltile[it] = tile; lrow[it] = row; lseg[it] = seg;
        ldst[it] = tile * TILE_B + SWZ(row * 128 + seg * 16);
    }

    float acc[2][8][4];
#pragma unroll
    for (int mi = 0; mi < 2; mi++)
#pragma unroll
        for (int ni = 0; ni < 8; ni++)
#pragma unroll
            for (int e = 0; e < 4; e++) acc[mi][ni][e] = 0.0f;

    // ------ pipeline ------
    auto issue_load = [&](int stage, int c) {
        int koff = c * 64;
        uint32_t base = sb + stage * STAGE_B;
#pragma unroll
        for (int it = 0; it < 16; it++) {
            const __nv_bfloat16* src0 =
                (ltile[it] == 0) ? Ahi : (ltile[it] == 1) ? Alo
              : (ltile[it] == 2) ? Bhi : Blo;
            int str = (ltile[it] < 2) ? strideA : strideB;
            const __nv_bfloat16* src = src0 + (size_t)lrow[it] * str + koff + lseg[it] * 8;
            CP16(base + ldst[it], src);
        }
        asm volatile("cp.async.commit_group;" ::: "memory");
    };

    issue_load(0, 0);

    // ldmatrix lane address components
    int a_r = lane & 15, a_h = (lane >> 4) << 4;       // A: row within m16, 16B half
    int b_r = lane & 7,  b_h = ((lane >> 3) & 1) << 4; // B: row within n8, 16B half

    for (int c = 0; c < nChunks; c++) {
        if (c + 1 < nChunks) {
            issue_load((c + 1) & 1, c + 1);
            asm volatile("cp.async.wait_group 1;" ::: "memory");
        } else {
            asm volatile("cp.async.wait_group 0;" ::: "memory");
        }
        __syncthreads();

        uint32_t st = sb + (c & 1) * STAGE_B;
        uint32_t aHiB = st;
        uint32_t aLoB = st + TILE_B;
        uint32_t bHiB = st + 2 * TILE_B;
        uint32_t bLoB = st + 3 * TILE_B;

#pragma unroll
        for (int kk = 0; kk < 4; kk++) {
            uint32_t ahi[2][4], alo[2][4];
#pragma unroll
            for (int mi = 0; mi < 2; mi++) {
                int row = wm * 32 + mi * 16 + a_r;
                uint32_t off = SWZ(row * 128 + kk * 32 + a_h);
                ldsm_x4(ahi[mi], aHiB + off);
                ldsm_x4(alo[mi], aLoB + off);
            }
#pragma unroll
            for (int ni = 0; ni < 8; ni++) {
                int row = wn * 64 + ni * 8 + b_r;
                uint32_t off = SWZ(row * 128 + kk * 32 + b_h);
                uint32_t bhi[2], blo[2];
                ldsm_x2(bhi, bHiB + off);
                ldsm_x2(blo, bLoB + off);
#pragma unroll
                for (int mi = 0; mi < 2; mi++) {
                    mma16816(acc[mi][ni], ahi[mi], bhi);
                    mma16816(acc[mi][ni], ahi[mi], blo);
                    mma16816(acc[mi][ni], alo[mi], bhi);
                }
            }
        }
        __syncthreads();
    }

    // ------ epilogue ------
    int g = lane >> 2, tq = lane & 3;
    const float scale = 0.08838834764831845f;
#pragma unroll
    for (int mi = 0; mi < 2; mi++) {
#pragma unroll
        for (int ni = 0; ni < 8; ni++) {
#pragma unroll
            for (int e = 0; e < 4; e++) {
                int row = wm * 32 + mi * 16 + g + ((e >> 1) << 3);
                int col = wn * 64 + ni * 8 + 2 * tq + (e & 1);
                float v = acc[mi][ni][e];
                if (mode == 0) {
                    int m = mtile * 128 + row;
                    int b = m >> 11, sx = m & 2047;
                    if (w == 0) {
                        size_t o = ((size_t)(b * NH + ntile) * S_LEN + sx) * HD + col;
                        split_st(v, g_Qhi + o, g_Qlo + o);
                    } else if (w == 1) {
                        size_t o = ((size_t)(b * NH + ntile) * S_LEN + sx) * HD + col;
                        split_st(v, g_Khi + o, g_Klo + o);
                    } else {
                        size_t o = (size_t)(b * NH + ntile) * HD * S_LEN
                                 + (size_t)col * S_LEN + sx;
                        split_st(v, g_Vthi + o, g_Vtlo + o);
                    }
                } else if (mode == 1) {
                    int q = qt * 128 + row, k = kt * 128 + col;
                    float s = (k <= q) ? v * scale : -1e30f;
                    size_t o = (size_t)z * S_LEN * S_LEN + (size_t)q * S_LEN + k;
                    split_st(s, g_Phi + o, g_Plo + o);
                } else if (mode == 2) {
                    int q = qt * 128 + row;
                    int b = z >> 4, hh = z & 15;
                    size_t o = ((size_t)b * S_LEN + q) * HID + hh * HD + col;
                    split_st(v, g_Chi + o, g_Clo + o);
                } else {
                    int m = mtile * 128 + row;
                    out[(size_t)m * HID + ntile * 128 + col] = v;
                }
            }
        }
    }
}

// ---------------------------------------------------------------------------
extern "C" void kernel_launch(void* const* d_in, const int* in_sizes, int n_in,
                              void* d_out, int out_size)
{
    (void)in_sizes; (void)n_in; (void)out_size;
    const float* X  = (const float*)d_in[0];
    const float* Wq = (const float*)d_in[3];
    const float* Wk = (const float*)d_in[4];
    const float* Wv = (const float*)d_in[5];
    const float* Wo = (const float*)d_in[6];
    float* out = (float*)d_out;

    cudaFuncSetAttribute(gemm_kernel,
                         cudaFuncAttributeMaxDynamicSharedMemorySize, SMEM_DYN);

    conv_kernel<<<32768, 256>>>(X, 4);
    conv_kernel<<<16384, 256>>>(Wq, 0);
    conv_kernel<<<16384, 256>>>(Wk, 1);
    conv_kernel<<<16384, 256>>>(Wv, 2);
    conv_kernel<<<16384, 256>>>(Wo, 3);

    gemm_kernel<<<1536, 256, SMEM_DYN>>>(0, nullptr);      // QKV proj
    rope_kernel<<<32768, 256>>>();
    gemm_kernel<<<4352, 256, SMEM_DYN>>>(1, nullptr);      // causal scores
    softmax_kernel<<<dim3(2048, 32), 256>>>();
    gemm_kernel<<<512, 256, SMEM_DYN>>>(2, nullptr);       // PV
    gemm_kernel<<<512, 256, SMEM_DYN>>>(3, out);           // out proj
}

// round 5
// speedup vs baseline: 2.2860x; 1.1718x over previous
#include <cuda_runtime.h>
#include <cuda_bf16.h>
#include <stdint.h>
#include <math.h>

#define S_LEN 2048
#define HID   2048
#define NH    16
#define HD    128
#define BATCH 2
#define MROWS 4096
#define NBH   32
#define TILE_B   16384            // 128 rows x 128 bytes
#define STAGE_B  (4 * TILE_B)
#define SMEM_GEMM (2 * STAGE_B)   // 128 KB
#define SMEM_FLASH (6 * 32768)    // Qh,Ql,Kh,Kl,Vh,Vl = 192 KB

// ---------------- scratch globals ------------------------------------------
__device__ __align__(16) __nv_bfloat16 g_Xhi[MROWS * HID];
__device__ __align__(16) __nv_bfloat16 g_Xlo[MROWS * HID];
__device__ __align__(16) __nv_bfloat16 g_Whi[4][HID * HID];   // Wq,Wk,Wv,Wo
__device__ __align__(16) __nv_bfloat16 g_Wlo[4][HID * HID];
__device__ __align__(16) __nv_bfloat16 g_Qhi[NBH * S_LEN * HD];
__device__ __align__(16) __nv_bfloat16 g_Qlo[NBH * S_LEN * HD];
__device__ __align__(16) __nv_bfloat16 g_Khi[NBH * S_LEN * HD];
__device__ __align__(16) __nv_bfloat16 g_Klo[NBH * S_LEN * HD];
__device__ __align__(16) __nv_bfloat16 g_Vhi[NBH * S_LEN * HD];   // natural [bh,s,d]
__device__ __align__(16) __nv_bfloat16 g_Vlo[NBH * S_LEN * HD];
__device__ __align__(16) __nv_bfloat16 g_Chi[MROWS * HID];
__device__ __align__(16) __nv_bfloat16 g_Clo[MROWS * HID];

// ---------------- helpers ---------------------------------------------------
__device__ __forceinline__ uint32_t smem_u32(const void* p) {
    uint32_t a;
    asm("{ .reg .u64 t; cvta.to.shared.u64 t, %1; cvt.u32.u64 %0, t; }"
        : "=r"(a) : "l"(p));
    return a;
}
#define SWZ(o) ((o) ^ (((o) >> 3) & 0x70))
#define CP16(dst, src) \
    asm volatile("cp.async.cg.shared.global [%0], [%1], 16;" \
                 :: "r"((uint32_t)(dst)), "l"(src) : "memory")

__device__ __forceinline__ void ldsm_x4(uint32_t r[4], uint32_t addr) {
    asm volatile("ldmatrix.sync.aligned.m8n8.x4.shared.b16 {%0,%1,%2,%3}, [%4];"
        : "=r"(r[0]), "=r"(r[1]), "=r"(r[2]), "=r"(r[3]) : "r"(addr));
}
__device__ __forceinline__ void ldsm_x4t(uint32_t r[4], uint32_t addr) {
    asm volatile("ldmatrix.sync.aligned.m8n8.x4.trans.shared.b16 {%0,%1,%2,%3}, [%4];"
        : "=r"(r[0]), "=r"(r[1]), "=r"(r[2]), "=r"(r[3]) : "r"(addr));
}
__device__ __forceinline__ void ldsm_x2(uint32_t r[2], uint32_t addr) {
    asm volatile("ldmatrix.sync.aligned.m8n8.x2.shared.b16 {%0,%1}, [%2];"
        : "=r"(r[0]), "=r"(r[1]) : "r"(addr));
}
__device__ __forceinline__ void mma16816(float d[4], const uint32_t a[4],
                                         const uint32_t b0, const uint32_t b1) {
    asm volatile("mma.sync.aligned.m16n8k16.row.col.f32.bf16.bf16.f32 "
        "{%0,%1,%2,%3}, {%4,%5,%6,%7}, {%8,%9}, {%0,%1,%2,%3};"
        : "+f"(d[0]), "+f"(d[1]), "+f"(d[2]), "+f"(d[3])
        : "r"(a[0]), "r"(a[1]), "r"(a[2]), "r"(a[3]), "r"(b0), "r"(b1));
}
__device__ __forceinline__ void split_st(float v, __nv_bfloat16* ph, __nv_bfloat16* pl) {
    __nv_bfloat16 h = __float2bfloat16_rn(v);
    *ph = h;
    *pl = __float2bfloat16_rn(v - __bfloat162float(h));
}
__device__ __forceinline__ uint32_t packbf(float a, float b) {
    __nv_bfloat162 t = __floats2bfloat162_rn(a, b);   // a -> .x (low)
    return *(uint32_t*)&t;
}

// ---------------- fp32 -> bf16 hi/lo conversion -----------------------------
__global__ void conv_kernel(const float* __restrict__ src, int which)
{
    int n = (which == 4) ? MROWS * HID : HID * HID;
    int i = blockIdx.x * 256 + threadIdx.x;
    if (i >= n) return;
    __nv_bfloat16 *dh, *dl;
    if (which == 4) { dh = g_Xhi; dl = g_Xlo; }
    else            { dh = g_Whi[which]; dl = g_Wlo[which]; }
    split_st(src[i], dh + i, dl + i);
}

// ---------------- RoPE on split Q/K in place ---------------------------------
__global__ void rope_kernel()
{
    const int half = NBH * S_LEN * 64;
    int idx = blockIdx.x * 256 + threadIdx.x;
    if (idx >= 2 * half) return;
    __nv_bfloat16 *bh, *bl;
    int r;
    if (idx < half) { bh = g_Qhi; bl = g_Qlo; r = idx; }
    else            { bh = g_Khi; bl = g_Klo; r = idx - half; }
    int i = r & 63;
    int row = r >> 6;
    int s = row & 2047;
    float invf = (float)(1.0 / pow(10000.0, (double)(2 * i) / 128.0));
    float ang = (float)s * invf;
    float c = cosf(ang), sn = sinf(ang);
    size_t base = (size_t)row * HD;
    float x1 = __bfloat162float(bh[base + i])      + __bfloat162float(bl[base + i]);
    float x2 = __bfloat162float(bh[base + i + 64]) + __bfloat162float(bl[base + i + 64]);
    split_st(x1 * c - x2 * sn, bh + base + i,      bl + base + i);
    split_st(x2 * c + x1 * sn, bh + base + i + 64, bl + base + i + 64);
}

// ---------------- projection / out-proj GEMM (mma.sync, split bf16) ---------
// modes: 0 = QKV proj, 3 = out proj
__global__ __launch_bounds__(256) void gemm_kernel(int mode, float* __restrict__ out)
{
    extern __shared__ char smem[];
    uint32_t sb = smem_u32(smem);

    int tid = threadIdx.x;
    int wid = tid >> 5, lane = tid & 31;
    int wm = wid & 3, wn = wid >> 2;
    int t = blockIdx.x;

    const __nv_bfloat16 *Ahi, *Alo, *Bhi, *Blo;
    int mtile, ntile, w = 0;
    const int nChunks = 32;

    if (mode == 0) {
        w = t >> 9; int r = t & 511; mtile = r >> 4; ntile = r & 15;
        Ahi = g_Xhi + (size_t)mtile * 128 * HID;
        Alo = g_Xlo + (size_t)mtile * 128 * HID;
        Bhi = g_Whi[w] + (size_t)ntile * 128 * HID;
        Blo = g_Wlo[w] + (size_t)ntile * 128 * HID;
    } else {
        mtile = t >> 4; ntile = t & 15;
        Ahi = g_Chi + (size_t)mtile * 128 * HID;
        Alo = g_Clo + (size_t)mtile * 128 * HID;
        Bhi = g_Whi[3] + (size_t)ntile * 128 * HID;
        Blo = g_Wlo[3] + (size_t)ntile * 128 * HID;
    }

    int lrow[16], lseg[16], ltile[16];
    uint32_t ldst[16];
#pragma unroll
    for (int it = 0; it < 16; it++) {
        int u = tid + it * 256;
        int tile = u >> 10;
        int v = u & 1023;
        int row = v >> 3, seg = v & 7;
        ltile[it] = tile; lrow[it] = row; lseg[it] = seg;
        ldst[it] = tile * TILE_B + SWZ(row * 128 + seg * 16);
    }

    float acc[2][8][4];
#pragma unroll
    for (int mi = 0; mi < 2; mi++)
#pragma unroll
        for (int ni = 0; ni < 8; ni++)
#pragma unroll
            for (int e = 0; e < 4; e++) acc[mi][ni][e] = 0.0f;

    auto issue_load = [&](int stage, int c) {
        int koff = c * 64;
        uint32_t base = sb + stage * STAGE_B;
#pragma unroll
        for (int it = 0; it < 16; it++) {
            const __nv_bfloat16* src0 =
                (ltile[it] == 0) ? Ahi : (ltile[it] == 1) ? Alo
              : (ltile[it] == 2) ? Bhi : Blo;
            const __nv_bfloat16* src = src0 + (size_t)lrow[it] * HID + koff + lseg[it] * 8;
            CP16(base + ldst[it], src);
        }
        asm volatile("cp.async.commit_group;" ::: "memory");
    };

    issue_load(0, 0);

    int a_r = lane & 15, a_h = (lane >> 4) << 4;
    int b_r = lane & 7,  b_h = ((lane >> 3) & 1) << 4;

    for (int c = 0; c < nChunks; c++) {
        if (c + 1 < nChunks) {
            issue_load((c + 1) & 1, c + 1);
            asm volatile("cp.async.wait_group 1;" ::: "memory");
        } else {
            asm volatile("cp.async.wait_group 0;" ::: "memory");
        }
        __syncthreads();

        uint32_t st = sb + (c & 1) * STAGE_B;
#pragma unroll
        for (int kk = 0; kk < 4; kk++) {
            uint32_t ahi[2][4], alo[2][4];
#pragma unroll
            for (int mi = 0; mi < 2; mi++) {
                int row = wm * 32 + mi * 16 + a_r;
                uint32_t off = SWZ(row * 128 + kk * 32 + a_h);
                ldsm_x4(ahi[mi], st + off);
                ldsm_x4(alo[mi], st + TILE_B + off);
            }
#pragma unroll
            for (int ni = 0; ni < 8; ni++) {
                int row = wn * 64 + ni * 8 + b_r;
                uint32_t off = SWZ(row * 128 + kk * 32 + b_h);
                uint32_t bhi[2], blo[2];
                ldsm_x2(bhi, st + 2 * TILE_B + off);
                ldsm_x2(blo, st + 3 * TILE_B + off);
#pragma unroll
                for (int mi = 0; mi < 2; mi++) {
                    mma16816(acc[mi][ni], ahi[mi], bhi[0], bhi[1]);
                    mma16816(acc[mi][ni], ahi[mi], blo[0], blo[1]);
                    mma16816(acc[mi][ni], alo[mi], bhi[0], bhi[1]);
                }
            }
        }
        __syncthreads();
    }

    int g = lane >> 2, tq = lane & 3;
#pragma unroll
    for (int mi = 0; mi < 2; mi++) {
#pragma unroll
        for (int ni = 0; ni < 8; ni++) {
#pragma unroll
            for (int e = 0; e < 4; e++) {
                int row = wm * 32 + mi * 16 + g + ((e >> 1) << 3);
                int col = wn * 64 + ni * 8 + 2 * tq + (e & 1);
                float v = acc[mi][ni][e];
                if (mode == 0) {
                    int m = mtile * 128 + row;
                    int b = m >> 11, sx = m & 2047;
                    size_t o = ((size_t)(b * NH + ntile) * S_LEN + sx) * HD + col;
                    if (w == 0)      split_st(v, g_Qhi + o, g_Qlo + o);
                    else if (w == 1) split_st(v, g_Khi + o, g_Klo + o);
                    else             split_st(v, g_Vhi + o, g_Vlo + o);
                } else {
                    int m = mtile * 128 + row;
                    out[(size_t)m * HID + ntile * 128 + col] = v;
                }
            }
        }
    }
}

// ---------------- fused flash attention -------------------------------------
// grid (16 qt, 32 bh), 256 threads (8 warps x 16 q-rows).
// S = (Qhi+Qlo)(Khi+Klo)^T * scale (3 terms), online softmax, P split hi/lo,
// O += (Phi+Plo)(Vhi+Vlo) (3 terms). Writes context split hi/lo.
__global__ __launch_bounds__(256, 1) void flash_kernel()
{
    extern __shared__ char smem[];
    uint32_t sb = smem_u32(smem);
    const uint32_t Qh = sb, Ql = sb + 32768;
    const uint32_t Kh = sb + 65536, Kl = sb + 98304;
    const uint32_t Vh = sb + 131072, Vl = sb + 163840;

    int qt = gridDim.x - 1 - blockIdx.x;     // heavy tiles first
    int z = blockIdx.y;
    int tid = threadIdx.x, wid = tid >> 5, lane = tid & 31;
    int g = lane >> 2, tq = lane & 3;

    const __nv_bfloat16* Qhg = g_Qhi + ((size_t)z * S_LEN + qt * 128) * HD;
    const __nv_bfloat16* Qlg = g_Qlo + ((size_t)z * S_LEN + qt * 128) * HD;
    const __nv_bfloat16* Khg = g_Khi + (size_t)z * S_LEN * HD;
    const __nv_bfloat16* Klg = g_Klo + (size_t)z * S_LEN * HD;
    const __nv_bfloat16* Vhg = g_Vhi + (size_t)z * S_LEN * HD;
    const __nv_bfloat16* Vlg = g_Vlo + (size_t)z * S_LEN * HD;

    // one [128][128] bf16 matrix = 2 halves of 16KB; 8 cp.async iters / matrix
    auto load_mat = [&](uint32_t dstbase, const __nv_bfloat16* src) {
#pragma unroll
        for (int it = 0; it < 8; it++) {
            int u = tid + it * 256;
            int row = u >> 4, c = u & 15;
            uint32_t dst = dstbase + ((c >> 3) << 14) + SWZ(row * 128 + (c & 7) * 16);
            CP16(dst, src + (size_t)row * HD + c * 8);
        }
    };

    load_mat(Qh, Qhg); load_mat(Ql, Qlg);
    asm volatile("cp.async.commit_group;" ::: "memory");
    load_mat(Kh, Khg); load_mat(Kl, Klg);
    asm volatile("cp.async.commit_group;" ::: "memory");
    load_mat(Vh, Vhg); load_mat(Vl, Vlg);
    asm volatile("cp.async.commit_group;" ::: "memory");

    float o[16][4];
#pragma unroll
    for (int j = 0; j < 16; j++)
#pragma unroll
        for (int e = 0; e < 4; e++) o[j][e] = 0.0f;
    float m0 = -3.4e38f, m1 = -3.4e38f, l0 = 0.0f, l1 = 0.0f;

    const float scale = 0.08838834764831845f;
    int a_r = lane & 15, a_h = (lane >> 4) << 4;
    int bsel = lane >> 3, br = lane & 7;

    for (int kt = 0; kt <= qt; kt++) {
        // ---- wait K (V still in flight) ----
        asm volatile("cp.async.wait_group 1;" ::: "memory");
        __syncthreads();

        // ---- S = Q K^T ----
        float s[16][4];
#pragma unroll
        for (int j = 0; j < 16; j++)
#pragma unroll
            for (int e = 0; e < 4; e++) s[j][e] = 0.0f;

#pragma unroll
        for (int kk = 0; kk < 8; kk++) {
            int arow = wid * 16 + a_r;
            uint32_t aoff = ((kk >> 2) << 14) + SWZ(arow * 128 + (kk & 3) * 32 + a_h);
            uint32_t ah[4], al[4];
            ldsm_x4(ah, Qh + aoff);
            ldsm_x4(al, Ql + aoff);
#pragma unroll
            for (int jp = 0; jp < 8; jp++) {
                int srow = jp * 16 + ((bsel >> 1) << 3) + br;
                uint32_t boff = ((kk >> 2) << 14)
                              + SWZ(srow * 128 + (kk & 3) * 32 + ((bsel & 1) << 4));
                uint32_t bh[4], bl[4];
                ldsm_x4(bh, Kh + boff);
                ldsm_x4(bl, Kl + boff);
                mma16816(s[2 * jp],     ah, bh[0], bh[1]);
                mma16816(s[2 * jp],     ah, bl[0], bl[1]);
                mma16816(s[2 * jp],     al, bh[0], bh[1]);
                mma16816(s[2 * jp + 1], ah, bh[2], bh[3]);
                mma16816(s[2 * jp + 1], ah, bl[2], bl[3]);
                mma16816(s[2 * jp + 1], al, bh[2], bh[3]);
            }
        }

        // ---- scale + causal mask + row max ----
        bool diag = (kt == qt);
        int row0 = qt * 128 + wid * 16 + g;
        float tm0 = -3.4e38f, tm1 = -3.4e38f;
#pragma unroll
        for (int j = 0; j < 16; j++) {
#pragma unroll
            for (int e = 0; e < 4; e++) {
                float v = s[j][e] * scale;
                if (diag) {
                    int col = kt * 128 + j * 8 + 2 * tq + (e & 1);
                    int row = row0 + ((e >> 1) << 3);
                    if (col > row) v = -3.0e38f;
                }
                s[j][e] = v;
                if (e < 2) tm0 = fmaxf(tm0, v); else tm1 = fmaxf(tm1, v);
            }
        }
        tm0 = fmaxf(tm0, __shfl_xor_sync(0xffffffffu, tm0, 1));
        tm0 = fmaxf(tm0, __shfl_xor_sync(0xffffffffu, tm0, 2));
        tm1 = fmaxf(tm1, __shfl_xor_sync(0xffffffffu, tm1, 1));
        tm1 = fmaxf(tm1, __shfl_xor_sync(0xffffffffu, tm1, 2));
        float nm0 = fmaxf(m0, tm0), nm1 = fmaxf(m1, tm1);
        float f0 = __expf(m0 - nm0), f1 = __expf(m1 - nm1);

        // ---- P = exp(S - m), split to bf16 A-frags, row sums ----
        float ts0 = 0.0f, ts1 = 0.0f;
        uint32_t phi[8][4], plo[8][4];
#pragma unroll
        for (int i = 0; i < 8; i++) {
            float p[2][4];
#pragma unroll
            for (int h = 0; h < 2; h++) {
                int j = 2 * i + h;
                p[h][0] = __expf(s[j][0] - nm0);
                p[h][1] = __expf(s[j][1] - nm0);
                p[h][2] = __expf(s[j][2] - nm1);
                p[h][3] = __expf(s[j][3] - nm1);
                ts0 += p[h][0] + p[h][1];
                ts1 += p[h][2] + p[h][3];
            }
            // a0=(g,klo) a1=(g+8,klo) a2=(g,khi) a3=(g+8,khi)
            phi[i][0] = packbf(p[0][0], p[0][1]);
            phi[i][1] = packbf(p[0][2], p[0][3]);
            phi[i][2] = packbf(p[1][0], p[1][1]);
            phi[i][3] = packbf(p[1][2], p[1][3]);
#pragma unroll
            for (int r = 0; r < 4; r++) {
                __nv_bfloat162 hb = *(__nv_bfloat162*)&phi[i][r];
                float e0 = ((r & 2) ? p[1] : p[0])[(r & 1) ? 2 : 0] - __bfloat162float(hb.x);
                float e1 = ((r & 2) ? p[1] : p[0])[(r & 1) ? 3 : 1] - __bfloat162float(hb.y);
                plo[i][r] = packbf(e0, e1);
            }
        }
        ts0 += __shfl_xor_sync(0xffffffffu, ts0, 1);
        ts0 += __shfl_xor_sync(0xffffffffu, ts0, 2);
        ts1 += __shfl_xor_sync(0xffffffffu, ts1, 1);
        ts1 += __shfl_xor_sync(0xffffffffu, ts1, 2);
        l0 = l0 * f0 + ts0;
        l1 = l1 * f1 + ts1;
        m0 = nm0; m1 = nm1;
#pragma unroll
        for (int j = 0; j < 16; j++) {
            o[j][0] *= f0; o[j][1] *= f0; o[j][2] *= f1; o[j][3] *= f1;
        }

        // ---- wait V; free K buffer; prefetch next K ----
        asm volatile("cp.async.wait_group 0;" ::: "memory");
        __syncthreads();
        if (kt < qt) {
            load_mat(Kh, Khg + (size_t)(kt + 1) * 128 * HD);
            load_mat(Kl, Klg + (size_t)(kt + 1) * 128 * HD);
            asm volatile("cp.async.commit_group;" ::: "memory");
        }

        // ---- O += P V ----
#pragma unroll
        for (int i = 0; i < 8; i++) {
#pragma unroll
            for (int dp = 0; dp < 8; dp++) {
                int krow = i * 16 + ((bsel & 1) << 3) + br;
                int dt = 2 * dp + (bsel >> 1);
                uint32_t voff = ((dt >> 3) << 14) + SWZ(krow * 128 + (dt & 7) * 16);
                uint32_t vh[4], vl[4];
                ldsm_x4t(vh, Vh + voff);
                ldsm_x4t(vl, Vl + voff);
                mma16816(o[2 * dp],     phi[i], vh[0], vh[1]);
                mma16816(o[2 * dp],     phi[i], vl[0], vl[1]);
                mma16816(o[2 * dp],     plo[i], vh[0], vh[1]);
                mma16816(o[2 * dp + 1], phi[i], vh[2], vh[3]);
                mma16816(o[2 * dp + 1], phi[i], vl[2], vl[3]);
                mma16816(o[2 * dp + 1], plo[i], vh[2], vh[3]);
            }
        }
        __syncthreads();       // all warps done reading V
        if (kt < qt) {
            load_mat(Vh, Vhg + (size_t)(kt + 1) * 128 * HD);
            load_mat(Vl, Vlg + (size_t)(kt + 1) * 128 * HD);
            asm volatile("cp.async.commit_group;" ::: "memory");
        }
    }

    // ---- epilogue: O /= l, write split context ----
    float inv0 = 1.0f / l0, inv1 = 1.0f / l1;
    int b = z >> 4, hh = z & 15;
#pragma unroll
    for (int dt = 0; dt < 16; dt++) {
#pragma unroll
        for (int e = 0; e < 4; e++) {
            int row = wid * 16 + g + ((e >> 1) << 3);
            int q = qt * 128 + row;
            int col = dt * 8 + 2 * tq + (e & 1);
            float v = o[dt][e] * ((e < 2) ? inv0 : inv1);
            size_t off = ((size_t)b * S_LEN + q) * HID + hh * HD + col;
            split_st(v, g_Chi + off, g_Clo + off);
        }
    }
}

// ---------------------------------------------------------------------------
extern "C" void kernel_launch(void* const* d_in, const int* in_sizes, int n_in,
                              void* d_out, int out_size)
{
    (void)in_sizes; (void)n_in; (void)out_size;
    const float* X  = (const float*)d_in[0];
    const float* Wq = (const float*)d_in[3];
    const float* Wk = (const float*)d_in[4];
    const float* Wv = (const float*)d_in[5];
    const float* Wo = (const float*)d_in[6];
    float* out = (float*)d_out;

    cudaFuncSetAttribute(gemm_kernel,
                         cudaFuncAttributeMaxDynamicSharedMemorySize, SMEM_GEMM);
    cudaFuncSetAttribute(flash_kernel,
                         cudaFuncAttributeMaxDynamicSharedMemorySize, SMEM_FLASH);

    conv_kernel<<<32768, 256>>>(X, 4);
    conv_kernel<<<16384, 256>>>(Wq, 0);
    conv_kernel<<<16384, 256>>>(Wk, 1);
    conv_kernel<<<16384, 256>>>(Wv, 2);
    conv_kernel<<<16384, 256>>>(Wo, 3);

    gemm_kernel<<<1536, 256, SMEM_GEMM>>>(0, nullptr);     // QKV proj
    rope_kernel<<<32768, 256>>>();
    flash_kernel<<<dim3(16, 32), 256, SMEM_FLASH>>>();     // fused attention
    gemm_kernel<<<512, 256, SMEM_GEMM>>>(3, out);          // out proj
}

// round 6
// speedup vs baseline: 2.3122x; 1.0115x over previous
#include <cuda_runtime.h>
#include <cuda_bf16.h>
#include <stdint.h>
#include <math.h>

#define S_LEN 2048
#define HID   2048
#define NH    16
#define HD    128
#define BATCH 2
#define MROWS 4096
#define NBH   32
// gemm: 256x128 block tile, stage = Ahi(32K)+Alo(32K)+Bhi(16K)+Blo(16K) = 96KB
#define G_STAGE   98304
#define SMEM_GEMM (2 * G_STAGE)      // 192 KB
#define SMEM_FLASH (6 * 32768)       // 192 KB

// ---------------- scratch globals ------------------------------------------
__device__ __align__(16) __nv_bfloat16 g_Xhi[MROWS * HID];
__device__ __align__(16) __nv_bfloat16 g_Xlo[MROWS * HID];
__device__ __align__(16) __nv_bfloat16 g_Whi[4][HID * HID];   // Wq,Wk,Wv,Wo
__device__ __align__(16) __nv_bfloat16 g_Wlo[4][HID * HID];
__device__ __align__(16) __nv_bfloat16 g_Qhi[NBH * S_LEN * HD];
__device__ __align__(16) __nv_bfloat16 g_Qlo[NBH * S_LEN * HD];
__device__ __align__(16) __nv_bfloat16 g_Khi[NBH * S_LEN * HD];
__device__ __align__(16) __nv_bfloat16 g_Klo[NBH * S_LEN * HD];
__device__ __align__(16) __nv_bfloat16 g_Vhi[NBH * S_LEN * HD];
__device__ __align__(16) __nv_bfloat16 g_Vlo[NBH * S_LEN * HD];
__device__ __align__(16) __nv_bfloat16 g_Chi[MROWS * HID];
__device__ __align__(16) __nv_bfloat16 g_Clo[MROWS * HID];

// ---------------- helpers ---------------------------------------------------
__device__ __forceinline__ uint32_t smem_u32(const void* p) {
    uint32_t a;
    asm("{ .reg .u64 t; cvta.to.shared.u64 t, %1; cvt.u32.u64 %0, t; }"
        : "=r"(a) : "l"(p));
    return a;
}
#define SWZ(o) ((o) ^ (((o) >> 3) & 0x70))
#define CP16(dst, src) \
    asm volatile("cp.async.cg.shared.global [%0], [%1], 16;" \
                 :: "r"((uint32_t)(dst)), "l"(src) : "memory")

__device__ __forceinline__ void ldsm_x4(uint32_t r[4], uint32_t addr) {
    asm volatile("ldmatrix.sync.aligned.m8n8.x4.shared.b16 {%0,%1,%2,%3}, [%4];"
        : "=r"(r[0]), "=r"(r[1]), "=r"(r[2]), "=r"(r[3]) : "r"(addr));
}
__device__ __forceinline__ void ldsm_x4t(uint32_t r[4], uint32_t addr) {
    asm volatile("ldmatrix.sync.aligned.m8n8.x4.trans.shared.b16 {%0,%1,%2,%3}, [%4];"
        : "=r"(r[0]), "=r"(r[1]), "=r"(r[2]), "=r"(r[3]) : "r"(addr));
}
__device__ __forceinline__ void mma16816(float d[4], const uint32_t a[4],
                                         const uint32_t b0, const uint32_t b1) {
    asm volatile("mma.sync.aligned.m16n8k16.row.col.f32.bf16.bf16.f32 "
        "{%0,%1,%2,%3}, {%4,%5,%6,%7}, {%8,%9}, {%0,%1,%2,%3};"
        : "+f"(d[0]), "+f"(d[1]), "+f"(d[2]), "+f"(d[3])
        : "r"(a[0]), "r"(a[1]), "r"(a[2]), "r"(a[3]), "r"(b0), "r"(b1));
}
__device__ __forceinline__ void split_st(float v, __nv_bfloat16* ph, __nv_bfloat16* pl) {
    __nv_bfloat16 h = __float2bfloat16_rn(v);
    *ph = h;
    *pl = __float2bfloat16_rn(v - __bfloat162float(h));
}
__device__ __forceinline__ uint32_t packbf(float a, float b) {
    __nv_bfloat162 t = __floats2bfloat162_rn(a, b);
    return *(uint32_t*)&t;
}

// ---------------- fused fp32 -> bf16 hi/lo conversion (one launch) ----------
__global__ void conv_kernel(const float* __restrict__ X,
                            const float* __restrict__ Wq, const float* __restrict__ Wk,
                            const float* __restrict__ Wv, const float* __restrict__ Wo)
{
    const int XN = MROWS * HID;          // 8388608
    const int WN = HID * HID;            // 4194304
    int i4 = (blockIdx.x * 256 + threadIdx.x) * 4;
    const float* src;
    __nv_bfloat16 *dh, *dl;
    int off;
    if (i4 < XN) { src = X; dh = g_Xhi; dl = g_Xlo; off = i4; }
    else {
        int j = i4 - XN;
        int w = j / WN; off = j - w * WN;
        src = (w == 0) ? Wq : (w == 1) ? Wk : (w == 2) ? Wv : Wo;
        dh = g_Whi[w]; dl = g_Wlo[w];
    }
    float4 v = *(const float4*)(src + off);
    __nv_bfloat16 h0, l0, h1, l1, h2, l2, h3, l3;
    h0 = __float2bfloat16_rn(v.x); l0 = __float2bfloat16_rn(v.x - __bfloat162float(h0));
    h1 = __float2bfloat16_rn(v.y); l1 = __float2bfloat16_rn(v.y - __bfloat162float(h1));
    h2 = __float2bfloat16_rn(v.z); l2 = __float2bfloat16_rn(v.z - __bfloat162float(h2));
    h3 = __float2bfloat16_rn(v.w); l3 = __float2bfloat16_rn(v.w - __bfloat162float(h3));
    ushort4 hv = { *(unsigned short*)&h0, *(unsigned short*)&h1,
                   *(unsigned short*)&h2, *(unsigned short*)&h3 };
    ushort4 lv = { *(unsigned short*)&l0, *(unsigned short*)&l1,
                   *(unsigned short*)&l2, *(unsigned short*)&l3 };
    *(ushort4*)(dh + off) = hv;
    *(ushort4*)(dl + off) = lv;
}

// ---------------- RoPE on split Q/K in place ---------------------------------
__global__ void rope_kernel()
{
    const int half = NBH * S_LEN * 64;
    int idx = blockIdx.x * 256 + threadIdx.x;
    if (idx >= 2 * half) return;
    __nv_bfloat16 *bh, *bl;
    int r;
    if (idx < half) { bh = g_Qhi; bl = g_Qlo; r = idx; }
    else            { bh = g_Khi; bl = g_Klo; r = idx - half; }
    int i = r & 63;
    int row = r >> 6;
    int s = row & 2047;
    float invf = (float)(1.0 / pow(10000.0, (double)(2 * i) / 128.0));
    float ang = (float)s * invf;
    float c = cosf(ang), sn = sinf(ang);
    size_t base = (size_t)row * HD;
    float x1 = __bfloat162float(bh[base + i])      + __bfloat162float(bl[base + i]);
    float x2 = __bfloat162float(bh[base + i + 64]) + __bfloat162float(bl[base + i + 64]);
    split_st(x1 * c - x2 * sn, bh + base + i,      bl + base + i);
    split_st(x2 * c + x1 * sn, bh + base + i + 64, bl + base + i + 64);
}

// ---------------- projection / out-proj GEMM (256x128 tile) -----------------
// modes: 0 = QKV proj, 3 = out proj. 8 warps: 4(M) x 2(N), warp tile 64x64.
__global__ __launch_bounds__(256, 1) void gemm_kernel(int mode, float* __restrict__ out)
{
    extern __shared__ char smem[];
    uint32_t sb = smem_u32(smem);

    int tid = threadIdx.x;
    int wid = tid >> 5, lane = tid & 31;
    int wm = wid >> 1, wn = wid & 1;
    int t = blockIdx.x;

    const __nv_bfloat16 *Ahi, *Alo, *Bhi, *Blo;
    int mtile, ntile, w = 0;
    const int nChunks = 32;

    if (mode == 0) {
        w = t >> 8; int r = t & 255; mtile = r >> 4; ntile = r & 15;
        Ahi = g_Xhi + (size_t)mtile * 256 * HID;
        Alo = g_Xlo + (size_t)mtile * 256 * HID;
        Bhi = g_Whi[w] + (size_t)ntile * 128 * HID;
        Blo = g_Wlo[w] + (size_t)ntile * 128 * HID;
    } else {
        mtile = t >> 4; ntile = t & 15;
        Ahi = g_Chi + (size_t)mtile * 256 * HID;
        Alo = g_Clo + (size_t)mtile * 256 * HID;
        Bhi = g_Whi[3] + (size_t)ntile * 128 * HID;
        Blo = g_Wlo[3] + (size_t)ntile * 128 * HID;
    }

    // 24 cp.async x 16B per thread per stage.
    // units: [0,2048) Ahi  [2048,4096) Alo  [4096,5120) Bhi  [5120,6144) Blo
    int lrow[24], lseg[24], lreg[24];
    uint32_t ldst[24];
#pragma unroll
    for (int it = 0; it < 24; it++) {
        int u = tid + it * 256;
        int reg = (u < 2048) ? 0 : (u < 4096) ? 1 : (u < 5120) ? 2 : 3;
        int v = u - ((reg == 0) ? 0 : (reg == 1) ? 2048 : (reg == 2) ? 4096 : 5120);
        int row = v >> 3, seg = v & 7;
        lreg[it] = reg; lrow[it] = row; lseg[it] = seg;
        uint32_t base = (reg == 0) ? 0u : (reg == 1) ? 32768u : (reg == 2) ? 65536u : 81920u;
        ldst[it] = base + SWZ(row * 128 + seg * 16);
    }

    float acc[4][8][4];
#pragma unroll
    for (int mi = 0; mi < 4; mi++)
#pragma unroll
        for (int ni = 0; ni < 8; ni++)
#pragma unroll
            for (int e = 0; e < 4; e++) acc[mi][ni][e] = 0.0f;

    auto issue_load = [&](int stage, int c) {
        int koff = c * 64;
        uint32_t base = sb + stage * G_STAGE;
#pragma unroll
        for (int it = 0; it < 24; it++) {
            const __nv_bfloat16* src0 =
                (lreg[it] == 0) ? Ahi : (lreg[it] == 1) ? Alo
              : (lreg[it] == 2) ? Bhi : Blo;
            const __nv_bfloat16* src = src0 + (size_t)lrow[it] * HID + koff + lseg[it] * 8;
            CP16(base + ldst[it], src);
        }
        asm volatile("cp.async.commit_group;" ::: "memory");
    };

    issue_load(0, 0);

    int a_r = lane & 15, a_h = (lane >> 4) << 4;           // A frag address
    int b_r = lane & 7;
    int b_row = ((lane >> 4) << 3) + b_r;                  // (sel>>1)*8 + br
    int b_h = ((lane >> 3) & 1) << 4;                      // (sel&1)*16

    for (int c = 0; c < nChunks; c++) {
        if (c + 1 < nChunks) {
            issue_load((c + 1) & 1, c + 1);
            asm volatile("cp.async.wait_group 1;" ::: "memory");
        } else {
            asm volatile("cp.async.wait_group 0;" ::: "memory");
        }
        __syncthreads();

        uint32_t st = sb + (c & 1) * G_STAGE;
        uint32_t aHiB = st, aLoB = st + 32768;
        uint32_t bHiB = st + 65536, bLoB = st + 81920;

#pragma unroll
        for (int kk = 0; kk < 4; kk++) {
            uint32_t ahi[4][4], alo[4][4];
#pragma unroll
            for (int mi = 0; mi < 4; mi++) {
                int row = wm * 64 + mi * 16 + a_r;
                uint32_t off = SWZ(row * 128 + kk * 32 + a_h);
                ldsm_x4(ahi[mi], aHiB + off);
                ldsm_x4(alo[mi], aLoB + off);
            }
#pragma unroll
            for (int np = 0; np < 4; np++) {
                int row = wn * 64 + np * 16 + b_row;
                uint32_t off = SWZ(row * 128 + kk * 32 + b_h);
                uint32_t bh[4], bl[4];
                ldsm_x4(bh, bHiB + off);
                ldsm_x4(bl, bLoB + off);
#pragma unroll
                for (int mi = 0; mi < 4; mi++) {
                    mma16816(acc[mi][2 * np],     ahi[mi], bh[0], bh[1]);
                    mma16816(acc[mi][2 * np],     ahi[mi], bl[0], bl[1]);
                    mma16816(acc[mi][2 * np],     alo[mi], bh[0], bh[1]);
                    mma16816(acc[mi][2 * np + 1], ahi[mi], bh[2], bh[3]);
                    mma16816(acc[mi][2 * np + 1], ahi[mi], bl[2], bl[3]);
                    mma16816(acc[mi][2 * np + 1], alo[mi], bh[2], bh[3]);
                }
            }
        }
        __syncthreads();
    }

    int g = lane >> 2, tq = lane & 3;
#pragma unroll
    for (int mi = 0; mi < 4; mi++) {
#pragma unroll
        for (int ni = 0; ni < 8; ni++) {
#pragma unroll
            for (int e = 0; e < 4; e++) {
                int row = wm * 64 + mi * 16 + g + ((e >> 1) << 3);
                int col = wn * 64 + ni * 8 + 2 * tq + (e & 1);
                float v = acc[mi][ni][e];
                if (mode == 0) {
                    int m = mtile * 256 + row;
                    int b = m >> 11, sx = m & 2047;
                    size_t o = ((size_t)(b * NH + ntile) * S_LEN + sx) * HD + col;
                    if (w == 0)      split_st(v, g_Qhi + o, g_Qlo + o);
                    else if (w == 1) split_st(v, g_Khi + o, g_Klo + o);
                    else             split_st(v, g_Vhi + o, g_Vlo + o);
                } else {
                    int m = mtile * 256 + row;
                    out[(size_t)m * HID + ntile * 128 + col] = v;
                }
            }
        }
    }
}

// ---------------- fused flash attention (unchanged from R5) ------------------
__global__ __launch_bounds__(256, 1) void flash_kernel()
{
    extern __shared__ char smem[];
    uint32_t sb = smem_u32(smem);
    const uint32_t Qh = sb, Ql = sb + 32768;
    const uint32_t Kh = sb + 65536, Kl = sb + 98304;
    const uint32_t Vh = sb + 131072, Vl = sb + 163840;

    int qt = gridDim.x - 1 - blockIdx.x;
    int z = blockIdx.y;
    int tid = threadIdx.x, wid = tid >> 5, lane = tid & 31;
    int g = lane >> 2, tq = lane & 3;

    const __nv_bfloat16* Qhg = g_Qhi + ((size_t)z * S_LEN + qt * 128) * HD;
    const __nv_bfloat16* Qlg = g_Qlo + ((size_t)z * S_LEN + qt * 128) * HD;
    const __nv_bfloat16* Khg = g_Khi + (size_t)z * S_LEN * HD;
    const __nv_bfloat16* Klg = g_Klo + (size_t)z * S_LEN * HD;
    const __nv_bfloat16* Vhg = g_Vhi + (size_t)z * S_LEN * HD;
    const __nv_bfloat16* Vlg = g_Vlo + (size_t)z * S_LEN * HD;

    auto load_mat = [&](uint32_t dstbase, const __nv_bfloat16* src) {
#pragma unroll
        for (int it = 0; it < 8; it++) {
            int u = tid + it * 256;
            int row = u >> 4, c = u & 15;
            uint32_t dst = dstbase + ((c >> 3) << 14) + SWZ(row * 128 + (c & 7) * 16);
            CP16(dst, src + (size_t)row * HD + c * 8);
        }
    };

    load_mat(Qh, Qhg); load_mat(Ql, Qlg);
    asm volatile("cp.async.commit_group;" ::: "memory");
    load_mat(Kh, Khg); load_mat(Kl, Klg);
    asm volatile("cp.async.commit_group;" ::: "memory");
    load_mat(Vh, Vhg); load_mat(Vl, Vlg);
    asm volatile("cp.async.commit_group;" ::: "memory");

    float o[16][4];
#pragma unroll
    for (int j = 0; j < 16; j++)
#pragma unroll
        for (int e = 0; e < 4; e++) o[j][e] = 0.0f;
    float m0 = -3.4e38f, m1 = -3.4e38f, l0 = 0.0f, l1 = 0.0f;

    const float scale = 0.08838834764831845f;
    int a_r = lane & 15, a_h = (lane >> 4) << 4;
    int bsel = lane >> 3, br = lane & 7;

    for (int kt = 0; kt <= qt; kt++) {
        asm volatile("cp.async.wait_group 1;" ::: "memory");
        __syncthreads();

        float s[16][4];
#pragma unroll
        for (int j = 0; j < 16; j++)
#pragma unroll
            for (int e = 0; e < 4; e++) s[j][e] = 0.0f;

#pragma unroll
        for (int kk = 0; kk < 8; kk++) {
            int arow = wid * 16 + a_r;
            uint32_t aoff = ((kk >> 2) << 14) + SWZ(arow * 128 + (kk & 3) * 32 + a_h);
            uint32_t ah[4], al[4];
            ldsm_x4(ah, Qh + aoff);
            ldsm_x4(al, Ql + aoff);
#pragma unroll
            for (int jp = 0; jp < 8; jp++) {
                int srow = jp * 16 + ((bsel >> 1) << 3) + br;
                uint32_t boff = ((kk >> 2) << 14)
                              + SWZ(srow * 128 + (kk & 3) * 32 + ((bsel & 1) << 4));
                uint32_t bh[4], bl[4];
                ldsm_x4(bh, Kh + boff);
                ldsm_x4(bl, Kl + boff);
                mma16816(s[2 * jp],     ah, bh[0], bh[1]);
                mma16816(s[2 * jp],     ah, bl[0], bl[1]);
                mma16816(s[2 * jp],     al, bh[0], bh[1]);
                mma16816(s[2 * jp + 1], ah, bh[2], bh[3]);
                mma16816(s[2 * jp + 1], ah, bl[2], bl[3]);
                mma16816(s[2 * jp + 1], al, bh[2], bh[3]);
            }
        }

        bool diag = (kt == qt);
        int row0 = qt * 128 + wid * 16 + g;
        float tm0 = -3.4e38f, tm1 = -3.4e38f;
#pragma unroll
        for (int j = 0; j < 16; j++) {
#pragma unroll
            for (int e = 0; e < 4; e++) {
                float v = s[j][e] * scale;
                if (diag) {
                    int col = kt * 128 + j * 8 + 2 * tq + (e & 1);
                    int row = row0 + ((e >> 1) << 3);
                    if (col > row) v = -3.0e38f;
                }
                s[j][e] = v;
                if (e < 2) tm0 = fmaxf(tm0, v); else tm1 = fmaxf(tm1, v);
            }
        }
        tm0 = fmaxf(tm0, __shfl_xor_sync(0xffffffffu, tm0, 1));
        tm0 = fmaxf(tm0, __shfl_xor_sync(0xffffffffu, tm0, 2));
        tm1 = fmaxf(tm1, __shfl_xor_sync(0xffffffffu, tm1, 1));
        tm1 = fmaxf(tm1, __shfl_xor_sync(0xffffffffu, tm1, 2));
        float nm0 = fmaxf(m0, tm0), nm1 = fmaxf(m1, tm1);
        float f0 = __expf(m0 - nm0), f1 = __expf(m1 - nm1);

        float ts0 = 0.0f, ts1 = 0.0f;
        uint32_t phi[8][4], plo[8][4];
#pragma unroll
        for (int i = 0; i < 8; i++) {
            float p[2][4];
#pragma unroll
            for (int h = 0; h < 2; h++) {
                int j = 2 * i + h;
                p[h][0] = __expf(s[j][0] - nm0);
                p[h][1] = __expf(s[j][1] - nm0);
                p[h][2] = __expf(s[j][2] - nm1);
                p[h][3] = __expf(s[j][3] - nm1);
                ts0 += p[h][0] + p[h][1];
                ts1 += p[h][2] + p[h][3];
            }
            phi[i][0] = packbf(p[0][0], p[0][1]);
            phi[i][1] = packbf(p[0][2], p[0][3]);
            phi[i][2] = packbf(p[1][0], p[1][1]);
            phi[i][3] = packbf(p[1][2], p[1][3]);
#pragma unroll
            for (int r = 0; r < 4; r++) {
                __nv_bfloat162 hb = *(__nv_bfloat162*)&phi[i][r];
                float e0 = ((r & 2) ? p[1] : p[0])[(r & 1) ? 2 : 0] - __bfloat162float(hb.x);
                float e1 = ((r & 2) ? p[1] : p[0])[(r & 1) ? 3 : 1] - __bfloat162float(hb.y);
                plo[i][r] = packbf(e0, e1);
            }
        }
        ts0 += __shfl_xor_sync(0xffffffffu, ts0, 1);
        ts0 += __shfl_xor_sync(0xffffffffu, ts0, 2);
        ts1 += __shfl_xor_sync(0xffffffffu, ts1, 1);
        ts1 += __shfl_xor_sync(0xffffffffu, ts1, 2);
        l0 = l0 * f0 + ts0;
        l1 = l1 * f1 + ts1;
        m0 = nm0; m1 = nm1;
#pragma unroll
        for (int j = 0; j < 16; j++) {
            o[j][0] *= f0; o[j][1] *= f0; o[j][2] *= f1; o[j][3] *= f1;
        }

        asm volatile("cp.async.wait_group 0;" ::: "memory");
        __syncthreads();
        if (kt < qt) {
            load_mat(Kh, Khg + (size_t)(kt + 1) * 128 * HD);
            load_mat(Kl, Klg + (size_t)(kt + 1) * 128 * HD);
            asm volatile("cp.async.commit_group;" ::: "memory");
        }

#pragma unroll
        for (int i = 0; i < 8; i++) {
#pragma unroll
            for (int dp = 0; dp < 8; dp++) {
                int krow = i * 16 + ((bsel & 1) << 3) + br;
                int dt = 2 * dp + (bsel >> 1);
                uint32_t voff = ((dt >> 3) << 14) + SWZ(krow * 128 + (dt & 7) * 16);
                uint32_t vh[4], vl[4];
                ldsm_x4t(vh, Vh + voff);
                ldsm_x4t(vl, Vl + voff);
                mma16816(o[2 * dp],     phi[i], vh[0], vh[1]);
                mma16816(o[2 * dp],     phi[i], vl[0], vl[1]);
                mma16816(o[2 * dp],     plo[i], vh[0], vh[1]);
                mma16816(o[2 * dp + 1], phi[i], vh[2], vh[3]);
                mma16816(o[2 * dp + 1], phi[i], vl[2], vl[3]);
                mma16816(o[2 * dp + 1], plo[i], vh[2], vh[3]);
            }
        }
        __syncthreads();
        if (kt < qt) {
            load_mat(Vh, Vhg + (size_t)(kt + 1) * 128 * HD);
            load_mat(Vl, Vlg + (size_t)(kt + 1) * 128 * HD);
            asm volatile("cp.async.commit_group;" ::: "memory");
        }
    }

    float inv0 = 1.0f / l0, inv1 = 1.0f / l1;
    int b = z >> 4, hh = z & 15;
#pragma unroll
    for (int dt = 0; dt < 16; dt++) {
#pragma unroll
        for (int e = 0; e < 4; e++) {
            int row = wid * 16 + g + ((e >> 1) << 3);
            int q = qt * 128 + row;
            int col = dt * 8 + 2 * tq + (e & 1);
            float v = o[dt][e] * ((e < 2) ? inv0 : inv1);
            size_t off = ((size_t)b * S_LEN + q) * HID + hh * HD + col;
            split_st(v, g_Chi + off, g_Clo + off);
        }
    }
}

// ---------------------------------------------------------------------------
extern "C" void kernel_launch(void* const* d_in, const int* in_sizes, int n_in,
                              void* d_out, int out_size)
{
    (void)in_sizes; (void)n_in; (void)out_size;
    const float* X  = (const float*)d_in[0];
    const float* Wq = (const float*)d_in[3];
    const float* Wk = (const float*)d_in[4];
    const float* Wv = (const float*)d_in[5];
    const float* Wo = (const float*)d_in[6];
    float* out = (float*)d_out;

    cudaFuncSetAttribute(gemm_kernel,
                         cudaFuncAttributeMaxDynamicSharedMemorySize, SMEM_GEMM);
    cudaFuncSetAttribute(flash_kernel,
                         cudaFuncAttributeMaxDynamicSharedMemorySize, SMEM_FLASH);

    conv_kernel<<<24576, 256>>>(X, Wq, Wk, Wv, Wo);        // all splits, 1 launch
    gemm_kernel<<<768, 256, SMEM_GEMM>>>(0, nullptr);      // QKV proj
    rope_kernel<<<32768, 256>>>();
    flash_kernel<<<dim3(16, 32), 256, SMEM_FLASH>>>();     // fused attention
    gemm_kernel<<<256, 256, SMEM_GEMM>>>(3, out);          // out proj
}

// round 7
// speedup vs baseline: 2.3290x; 1.0072x over previous
#include <cuda_runtime.h>
#include <cuda_bf16.h>
#include <stdint.h>
#include <math.h>

#define S_LEN 2048
#define HID   2048
#define NH    16
#define HD    128
#define BATCH 2
#define MROWS 4096
#define NBH   32
#define TILE_B   16384            // 128 rows x 128 bytes
#define STAGE_B  (4 * TILE_B)     // 64 KB
#define SMEM_GEMM (2 * STAGE_B)   // 128 KB
#define SMEM_FLASH (6 * 32768)    // 192 KB

// ---------------- scratch globals ------------------------------------------
__device__ __align__(16) __nv_bfloat16 g_Xhi[MROWS * HID];
__device__ __align__(16) __nv_bfloat16 g_Xlo[MROWS * HID];
__device__ __align__(16) __nv_bfloat16 g_Whi[4][HID * HID];
__device__ __align__(16) __nv_bfloat16 g_Wlo[4][HID * HID];
__device__ __align__(16) __nv_bfloat16 g_Qhi[NBH * S_LEN * HD];
__device__ __align__(16) __nv_bfloat16 g_Qlo[NBH * S_LEN * HD];
__device__ __align__(16) __nv_bfloat16 g_Khi[NBH * S_LEN * HD];
__device__ __align__(16) __nv_bfloat16 g_Klo[NBH * S_LEN * HD];
__device__ __align__(16) __nv_bfloat16 g_Vhi[NBH * S_LEN * HD];
__device__ __align__(16) __nv_bfloat16 g_Vlo[NBH * S_LEN * HD];
__device__ __align__(16) __nv_bfloat16 g_Chi[MROWS * HID];
__device__ __align__(16) __nv_bfloat16 g_Clo[MROWS * HID];

// ---------------- helpers ---------------------------------------------------
__device__ __forceinline__ uint32_t smem_u32(const void* p) {
    uint32_t a;
    asm("{ .reg .u64 t; cvta.to.shared.u64 t, %1; cvt.u32.u64 %0, t; }"
        : "=r"(a) : "l"(p));
    return a;
}
#define SWZ(o) ((o) ^ (((o) >> 3) & 0x70))
#define CP16(dst, src) \
    asm volatile("cp.async.cg.shared.global [%0], [%1], 16;" \
                 :: "r"((uint32_t)(dst)), "l"(src) : "memory")

__device__ __forceinline__ void ldsm_x4(uint32_t r[4], uint32_t addr) {
    asm volatile("ldmatrix.sync.aligned.m8n8.x4.shared.b16 {%0,%1,%2,%3}, [%4];"
        : "=r"(r[0]), "=r"(r[1]), "=r"(r[2]), "=r"(r[3]) : "r"(addr));
}
__device__ __forceinline__ void ldsm_x4t(uint32_t r[4], uint32_t addr) {
    asm volatile("ldmatrix.sync.aligned.m8n8.x4.trans.shared.b16 {%0,%1,%2,%3}, [%4];"
        : "=r"(r[0]), "=r"(r[1]), "=r"(r[2]), "=r"(r[3]) : "r"(addr));
}
__device__ __forceinline__ void mma16816(float d[4], const uint32_t a[4],
                                         const uint32_t b0, const uint32_t b1) {
    asm volatile("mma.sync.aligned.m16n8k16.row.col.f32.bf16.bf16.f32 "
        "{%0,%1,%2,%3}, {%4,%5,%6,%7}, {%8,%9}, {%0,%1,%2,%3};"
        : "+f"(d[0]), "+f"(d[1]), "+f"(d[2]), "+f"(d[3])
        : "r"(a[0]), "r"(a[1]), "r"(a[2]), "r"(a[3]), "r"(b0), "r"(b1));
}
__device__ __forceinline__ void split_st(float v, __nv_bfloat16* ph, __nv_bfloat16* pl) {
    __nv_bfloat16 h = __float2bfloat16_rn(v);
    *ph = h;
    *pl = __float2bfloat16_rn(v - __bfloat162float(h));
}
__device__ __forceinline__ uint32_t packbf(float a, float b) {
    __nv_bfloat162 t = __floats2bfloat162_rn(a, b);
    return *(uint32_t*)&t;
}

// ---------------- fused fp32 -> bf16 hi/lo conversion ------------------------
__global__ void conv_kernel(const float* __restrict__ X,
                            const float* __restrict__ Wq, const float* __restrict__ Wk,
                            const float* __restrict__ Wv, const float* __restrict__ Wo)
{
    const int XN = MROWS * HID;
    const int WN = HID * HID;
    int i4 = (blockIdx.x * 256 + threadIdx.x) * 4;
    const float* src;
    __nv_bfloat16 *dh, *dl;
    int off;
    if (i4 < XN) { src = X; dh = g_Xhi; dl = g_Xlo; off = i4; }
    else {
        int j = i4 - XN;
        int w = j / WN; off = j - w * WN;
        src = (w == 0) ? Wq : (w == 1) ? Wk : (w == 2) ? Wv : Wo;
        dh = g_Whi[w]; dl = g_Wlo[w];
    }
    float4 v = *(const float4*)(src + off);
    __nv_bfloat16 h0, l0, h1, l1, h2, l2, h3, l3;
    h0 = __float2bfloat16_rn(v.x); l0 = __float2bfloat16_rn(v.x - __bfloat162float(h0));
    h1 = __float2bfloat16_rn(v.y); l1 = __float2bfloat16_rn(v.y - __bfloat162float(h1));
    h2 = __float2bfloat16_rn(v.z); l2 = __float2bfloat16_rn(v.z - __bfloat162float(h2));
    h3 = __float2bfloat16_rn(v.w); l3 = __float2bfloat16_rn(v.w - __bfloat162float(h3));
    ushort4 hv = { *(unsigned short*)&h0, *(unsigned short*)&h1,
                   *(unsigned short*)&h2, *(unsigned short*)&h3 };
    ushort4 lv = { *(unsigned short*)&l0, *(unsigned short*)&l1,
                   *(unsigned short*)&l2, *(unsigned short*)&l3 };
    *(ushort4*)(dh + off) = hv;
    *(ushort4*)(dl + off) = lv;
}

// ---------------- RoPE on split Q/K in place ---------------------------------
__global__ void rope_kernel()
{
    const int half = NBH * S_LEN * 64;
    int idx = blockIdx.x * 256 + threadIdx.x;
    if (idx >= 2 * half) return;
    __nv_bfloat16 *bh, *bl;
    int r;
    if (idx < half) { bh = g_Qhi; bl = g_Qlo; r = idx; }
    else            { bh = g_Khi; bl = g_Klo; r = idx - half; }
    int i = r & 63;
    int row = r >> 6;
    int s = row & 2047;
    float invf = (float)(1.0 / pow(10000.0, (double)(2 * i) / 128.0));
    float ang = (float)s * invf;
    float c = cosf(ang), sn = sinf(ang);
    size_t base = (size_t)row * HD;
    float x1 = __bfloat162float(bh[base + i])      + __bfloat162float(bl[base + i]);
    float x2 = __bfloat162float(bh[base + i + 64]) + __bfloat162float(bl[base + i + 64]);
    split_st(x1 * c - x2 * sn, bh + base + i,      bl + base + i);
    split_st(x2 * c + x1 * sn, bh + base + i + 64, bl + base + i + 64);
}

// ---------------- projection / out-proj GEMM (128x128 tile) -----------------
// 8 warps: 4(M) x 2(N), warp tile 32x64. MMA terms interleaved across 8 accs.
__global__ __launch_bounds__(256, 1) void gemm_kernel(int mode, float* __restrict__ out)
{
    extern __shared__ char smem[];
    uint32_t sb = smem_u32(smem);

    int tid = threadIdx.x;
    int wid = tid >> 5, lane = tid & 31;
    int wm = wid & 3, wn = wid >> 2;
    int t = blockIdx.x;

    const __nv_bfloat16 *Ahi, *Alo, *Bhi, *Blo;
    int mtile, ntile, w = 0;
    const int nChunks = 32;

    if (mode == 0) {
        w = t >> 9; int r = t & 511; mtile = r >> 4; ntile = r & 15;
        Ahi = g_Xhi + (size_t)mtile * 128 * HID;
        Alo = g_Xlo + (size_t)mtile * 128 * HID;
        Bhi = g_Whi[w] + (size_t)ntile * 128 * HID;
        Blo = g_Wlo[w] + (size_t)ntile * 128 * HID;
    } else {
        mtile = t >> 4; ntile = t & 15;
        Ahi = g_Chi + (size_t)mtile * 128 * HID;
        Alo = g_Clo + (size_t)mtile * 128 * HID;
        Bhi = g_Whi[3] + (size_t)ntile * 128 * HID;
        Blo = g_Wlo[3] + (size_t)ntile * 128 * HID;
    }

    int lrow[16], lseg[16], ltile[16];
    uint32_t ldst[16];
#pragma unroll
    for (int it = 0; it < 16; it++) {
        int u = tid + it * 256;
        int tile = u >> 10;
        int v = u & 1023;
        int row = v >> 3, seg = v & 7;
        ltile[it] = tile; lrow[it] = row; lseg[it] = seg;
        ldst[it] = tile * TILE_B + SWZ(row * 128 + seg * 16);
    }

    float acc[2][8][4];
#pragma unroll
    for (int mi = 0; mi < 2; mi++)
#pragma unroll
        for (int ni = 0; ni < 8; ni++)
#pragma unroll
            for (int e = 0; e < 4; e++) acc[mi][ni][e] = 0.0f;

    auto issue_load = [&](int stage, int c) {
        int koff = c * 64;
        uint32_t base = sb + stage * STAGE_B;
#pragma unroll
        for (int it = 0; it < 16; it++) {
            const __nv_bfloat16* src0 =
                (ltile[it] == 0) ? Ahi : (ltile[it] == 1) ? Alo
              : (ltile[it] == 2) ? Bhi : Blo;
            const __nv_bfloat16* src = src0 + (size_t)lrow[it] * HID + koff + lseg[it] * 8;
            CP16(base + ldst[it], src);
        }
        asm volatile("cp.async.commit_group;" ::: "memory");
    };

    issue_load(0, 0);

    int a_r = lane & 15, a_h = (lane >> 4) << 4;
    int b_r = lane & 7;
    int b_row = ((lane >> 4) << 3) + b_r;
    int b_h = ((lane >> 3) & 1) << 4;

    for (int c = 0; c < nChunks; c++) {
        if (c + 1 < nChunks) {
            issue_load((c + 1) & 1, c + 1);
            asm volatile("cp.async.wait_group 1;" ::: "memory");
        } else {
            asm volatile("cp.async.wait_group 0;" ::: "memory");
        }
        __syncthreads();

        uint32_t st = sb + (c & 1) * STAGE_B;
        uint32_t aHiB = st, aLoB = st + TILE_B;
        uint32_t bHiB = st + 2 * TILE_B, bLoB = st + 3 * TILE_B;

#pragma unroll
        for (int kk = 0; kk < 4; kk++) {
            uint32_t ahi[2][4], alo[2][4];
#pragma unroll
            for (int mi = 0; mi < 2; mi++) {
                int row = wm * 32 + mi * 16 + a_r;
                uint32_t off = SWZ(row * 128 + kk * 32 + a_h);
                ldsm_x4(ahi[mi], aHiB + off);
                ldsm_x4(alo[mi], aLoB + off);
            }
#pragma unroll
            for (int np = 0; np < 4; np += 2) {
                int row0 = wn * 64 + np * 16 + b_row;
                int row1 = wn * 64 + (np + 1) * 16 + b_row;
                uint32_t off0 = SWZ(row0 * 128 + kk * 32 + b_h);
                uint32_t off1 = SWZ(row1 * 128 + kk * 32 + b_h);
                uint32_t bh0[4], bl0[4], bh1[4], bl1[4];
                ldsm_x4(bh0, bHiB + off0);
                ldsm_x4(bl0, bLoB + off0);
                ldsm_x4(bh1, bHiB + off1);
                ldsm_x4(bl1, bLoB + off1);
                // hh: 8 distinct accumulators
                mma16816(acc[0][2*np],   ahi[0], bh0[0], bh0[1]);
                mma16816(acc[1][2*np],   ahi[1], bh0[0], bh0[1]);
                mma16816(acc[0][2*np+1], ahi[0], bh0[2], bh0[3]);
                mma16816(acc[1][2*np+1], ahi[1], bh0[2], bh0[3]);
                mma16816(acc[0][2*np+2], ahi[0], bh1[0], bh1[1]);
                mma16816(acc[1][2*np+2], ahi[1], bh1[0], bh1[1]);
                mma16816(acc[0][2*np+3], ahi[0], bh1[2], bh1[3]);
                mma16816(acc[1][2*np+3], ahi[1], bh1[2], bh1[3]);
                // hl
                mma16816(acc[0][2*np],   ahi[0], bl0[0], bl0[1]);
                mma16816(acc[1][2*np],   ahi[1], bl0[0], bl0[1]);
                mma16816(acc[0][2*np+1], ahi[0], bl0[2], bl0[3]);
                mma16816(acc[1][2*np+1], ahi[1], bl0[2], bl0[3]);
                mma16816(acc[0][2*np+2], ahi[0], bl1[0], bl1[1]);
                mma16816(acc[1][2*np+2], ahi[1], bl1[0], bl1[1]);
                mma16816(acc[0][2*np+3], ahi[0], bl1[2], bl1[3]);
                mma16816(acc[1][2*np+3], ahi[1], bl1[2], bl1[3]);
                // lh
                mma16816(acc[0][2*np],   alo[0], bh0[0], bh0[1]);
                mma16816(acc[1][2*np],   alo[1], bh0[0], bh0[1]);
                mma16816(acc[0][2*np+1], alo[0], bh0[2], bh0[3]);
                mma16816(acc[1][2*np+1], alo[1], bh0[2], bh0[3]);
                mma16816(acc[0][2*np+2], alo[0], bh1[0], bh1[1]);
                mma16816(acc[1][2*np+2], alo[1], bh1[0], bh1[1]);
                mma16816(acc[0][2*np+3], alo[0], bh1[2], bh1[3]);
                mma16816(acc[1][2*np+3], alo[1], bh1[2], bh1[3]);
            }
        }
        __syncthreads();
    }

    int g = lane >> 2, tq = lane & 3;
#pragma unroll
    for (int mi = 0; mi < 2; mi++) {
#pragma unroll
        for (int ni = 0; ni < 8; ni++) {
#pragma unroll
            for (int e = 0; e < 4; e++) {
                int row = wm * 32 + mi * 16 + g + ((e >> 1) << 3);
                int col = wn * 64 + ni * 8 + 2 * tq + (e & 1);
                float v = acc[mi][ni][e];
                if (mode == 0) {
                    int m = mtile * 128 + row;
                    int b = m >> 11, sx = m & 2047;
                    size_t o = ((size_t)(b * NH + ntile) * S_LEN + sx) * HD + col;
                    if (w == 0)      split_st(v, g_Qhi + o, g_Qlo + o);
                    else if (w == 1) split_st(v, g_Khi + o, g_Klo + o);
                    else             split_st(v, g_Vhi + o, g_Vlo + o);
                } else {
                    int m = mtile * 128 + row;
                    out[(size_t)m * HID + ntile * 128 + col] = v;
                }
            }
        }
    }
}

// ---------------- fused flash attention (interleaved MMA ordering) -----------
__global__ __launch_bounds__(256, 1) void flash_kernel()
{
    extern __shared__ char smem[];
    uint32_t sb = smem_u32(smem);
    const uint32_t Qh = sb, Ql = sb + 32768;
    const uint32_t Kh = sb + 65536, Kl = sb + 98304;
    const uint32_t Vh = sb + 131072, Vl = sb + 163840;

    int qt = gridDim.x - 1 - blockIdx.x;
    int z = blockIdx.y;
    int tid = threadIdx.x, wid = tid >> 5, lane = tid & 31;
    int g = lane >> 2, tq = lane & 3;

    const __nv_bfloat16* Qhg = g_Qhi + ((size_t)z * S_LEN + qt * 128) * HD;
    const __nv_bfloat16* Qlg = g_Qlo + ((size_t)z * S_LEN + qt * 128) * HD;
    const __nv_bfloat16* Khg = g_Khi + (size_t)z * S_LEN * HD;
    const __nv_bfloat16* Klg = g_Klo + (size_t)z * S_LEN * HD;
    const __nv_bfloat16* Vhg = g_Vhi + (size_t)z * S_LEN * HD;
    const __nv_bfloat16* Vlg = g_Vlo + (size_t)z * S_LEN * HD;

    auto load_mat = [&](uint32_t dstbase, const __nv_bfloat16* src) {
#pragma unroll
        for (int it = 0; it < 8; it++) {
            int u = tid + it * 256;
            int row = u >> 4, c = u & 15;
            uint32_t dst = dstbase + ((c >> 3) << 14) + SWZ(row * 128 + (c & 7) * 16);
            CP16(dst, src + (size_t)row * HD + c * 8);
        }
    };

    load_mat(Qh, Qhg); load_mat(Ql, Qlg);
    asm volatile("cp.async.commit_group;" ::: "memory");
    load_mat(Kh, Khg); load_mat(Kl, Klg);
    asm volatile("cp.async.commit_group;" ::: "memory");
    load_mat(Vh, Vhg); load_mat(Vl, Vlg);
    asm volatile("cp.async.commit_group;" ::: "memory");

    float o[16][4];
#pragma unroll
    for (int j = 0; j < 16; j++)
#pragma unroll
        for (int e = 0; e < 4; e++) o[j][e] = 0.0f;
    float m0 = -3.4e38f, m1 = -3.4e38f, l0 = 0.0f, l1 = 0.0f;

    const float scale = 0.08838834764831845f;
    int a_r = lane & 15, a_h = (lane >> 4) << 4;
    int bsel = lane >> 3, br = lane & 7;

    for (int kt = 0; kt <= qt; kt++) {
        asm volatile("cp.async.wait_group 1;" ::: "memory");
        __syncthreads();

        float s[16][4];
#pragma unroll
        for (int j = 0; j < 16; j++)
#pragma unroll
            for (int e = 0; e < 4; e++) s[j][e] = 0.0f;

#pragma unroll
        for (int kk = 0; kk < 8; kk++) {
            int arow = wid * 16 + a_r;
            uint32_t aoff = ((kk >> 2) << 14) + SWZ(arow * 128 + (kk & 3) * 32 + a_h);
            uint32_t ah[4], al[4];
            ldsm_x4(ah, Qh + aoff);
            ldsm_x4(al, Ql + aoff);
#pragma unroll
            for (int jp = 0; jp < 8; jp += 2) {
                int srow0 = jp * 16 + ((bsel >> 1) << 3) + br;
                int srow1 = (jp + 1) * 16 + ((bsel >> 1) << 3) + br;
                uint32_t boff0 = ((kk >> 2) << 14)
                               + SWZ(srow0 * 128 + (kk & 3) * 32 + ((bsel & 1) << 4));
                uint32_t boff1 = ((kk >> 2) << 14)
                               + SWZ(srow1 * 128 + (kk & 3) * 32 + ((bsel & 1) << 4));
                uint32_t bh0[4], bl0[4], bh1[4], bl1[4];
                ldsm_x4(bh0, Kh + boff0);
                ldsm_x4(bl0, Kl + boff0);
                ldsm_x4(bh1, Kh + boff1);
                ldsm_x4(bl1, Kl + boff1);
                // hh across 4 distinct accs
                mma16816(s[2*jp],   ah, bh0[0], bh0[1]);
                mma16816(s[2*jp+1], ah, bh0[2], bh0[3]);
                mma16816(s[2*jp+2], ah, bh1[0], bh1[1]);
                mma16816(s[2*jp+3], ah, bh1[2], bh1[3]);
                // hl
                mma16816(s[2*jp],   ah, bl0[0], bl0[1]);
                mma16816(s[2*jp+1], ah, bl0[2], bl0[3]);
                mma16816(s[2*jp+2], ah, bl1[0], bl1[1]);
                mma16816(s[2*jp+3], ah, bl1[2], bl1[3]);
                // lh
                mma16816(s[2*jp],   al, bh0[0], bh0[1]);
                mma16816(s[2*jp+1], al, bh0[2], bh0[3]);
                mma16816(s[2*jp+2], al, bh1[0], bh1[1]);
                mma16816(s[2*jp+3], al, bh1[2], bh1[3]);
            }
        }

        bool diag = (kt == qt);
        int row0 = qt * 128 + wid * 16 + g;
        float tm0 = -3.4e38f, tm1 = -3.4e38f;
#pragma unroll
        for (int j = 0; j < 16; j++) {
#pragma unroll
            for (int e = 0; e < 4; e++) {
                float v = s[j][e] * scale;
                if (diag) {
                    int col = kt * 128 + j * 8 + 2 * tq + (e & 1);
                    int row = row0 + ((e >> 1) << 3);
                    if (col > row) v = -3.0e38f;
                }
                s[j][e] = v;
                if (e < 2) tm0 = fmaxf(tm0, v); else tm1 = fmaxf(tm1, v);
            }
        }
        tm0 = fmaxf(tm0, __shfl_xor_sync(0xffffffffu, tm0, 1));
        tm0 = fmaxf(tm0, __shfl_xor_sync(0xffffffffu, tm0, 2));
        tm1 = fmaxf(tm1, __shfl_xor_sync(0xffffffffu, tm1, 1));
        tm1 = fmaxf(tm1, __shfl_xor_sync(0xffffffffu, tm1, 2));
        float nm0 = fmaxf(m0, tm0), nm1 = fmaxf(m1, tm1);
        float f0 = __expf(m0 - nm0), f1 = __expf(m1 - nm1);

        float ts0 = 0.0f, ts1 = 0.0f;
        uint32_t phi[8][4], plo[8][4];
#pragma unroll
        for (int i = 0; i < 8; i++) {
            float p[2][4];
#pragma unroll
            for (int h = 0; h < 2; h++) {
                int j = 2 * i + h;
                p[h][0] = __expf(s[j][0] - nm0);
                p[h][1] = __expf(s[j][1] - nm0);
                p[h][2] = __expf(s[j][2] - nm1);
                p[h][3] = __expf(s[j][3] - nm1);
                ts0 += p[h][0] + p[h][1];
                ts1 += p[h][2] + p[h][3];
            }
            phi[i][0] = packbf(p[0][0], p[0][1]);
            phi[i][1] = packbf(p[0][2], p[0][3]);
            phi[i][2] = packbf(p[1][0], p[1][1]);
            phi[i][3] = packbf(p[1][2], p[1][3]);
#pragma unroll
            for (int r = 0; r < 4; r++) {
                __nv_bfloat162 hb = *(__nv_bfloat162*)&phi[i][r];
                float e0 = ((r & 2) ? p[1] : p[0])[(r & 1) ? 2 : 0] - __bfloat162float(hb.x);
                float e1 = ((r & 2) ? p[1] : p[0])[(r & 1) ? 3 : 1] - __bfloat162float(hb.y);
                plo[i][r] = packbf(e0, e1);
            }
        }
        ts0 += __shfl_xor_sync(0xffffffffu, ts0, 1);
        ts0 += __shfl_xor_sync(0xffffffffu, ts0, 2);
        ts1 += __shfl_xor_sync(0xffffffffu, ts1, 1);
        ts1 += __shfl_xor_sync(0xffffffffu, ts1, 2);
        l0 = l0 * f0 + ts0;
        l1 = l1 * f1 + ts1;
        m0 = nm0; m1 = nm1;
#pragma unroll
        for (int j = 0; j < 16; j++) {
            o[j][0] *= f0; o[j][1] *= f0; o[j][2] *= f1; o[j][3] *= f1;
        }

        asm volatile("cp.async.wait_group 0;" ::: "memory");
        __syncthreads();
        if (kt < qt) {
            load_mat(Kh, Khg + (size_t)(kt + 1) * 128 * HD);
            load_mat(Kl, Klg + (size_t)(kt + 1) * 128 * HD);
            asm volatile("cp.async.commit_group;" ::: "memory");
        }

#pragma unroll
        for (int i = 0; i < 8; i++) {
            int krow = i * 16 + ((bsel & 1) << 3) + br;
#pragma unroll
            for (int dp = 0; dp < 8; dp += 2) {
                int dt0 = 2 * dp + (bsel >> 1);
                int dt1 = 2 * (dp + 1) + (bsel >> 1);
                uint32_t voff0 = ((dt0 >> 3) << 14) + SWZ(krow * 128 + (dt0 & 7) * 16);
                uint32_t voff1 = ((dt1 >> 3) << 14) + SWZ(krow * 128 + (dt1 & 7) * 16);
                uint32_t vh0[4], vl0[4], vh1[4], vl1[4];
                ldsm_x4t(vh0, Vh + voff0);
                ldsm_x4t(vl0, Vl + voff0);
                ldsm_x4t(vh1, Vh + voff1);
                ldsm_x4t(vl1, Vl + voff1);
                // hh across 4 distinct accs
                mma16816(o[2*dp],   phi[i], vh0[0], vh0[1]);
                mma16816(o[2*dp+1], phi[i], vh0[2], vh0[3]);
                mma16816(o[2*dp+2], phi[i], vh1[0], vh1[1]);
                mma16816(o[2*dp+3], phi[i], vh1[2], vh1[3]);
                // hl
                mma16816(o[2*dp],   phi[i], vl0[0], vl0[1]);
                mma16816(o[2*dp+1], phi[i], vl0[2], vl0[3]);
                mma16816(o[2*dp+2], phi[i], vl1[0], vl1[1]);
                mma16816(o[2*dp+3], phi[i], vl1[2], vl1[3]);
                // lh
                mma16816(o[2*dp],   plo[i], vh0[0], vh0[1]);
                mma16816(o[2*dp+1], plo[i], vh0[2], vh0[3]);
                mma16816(o[2*dp+2], plo[i], vh1[0], vh1[1]);
                mma16816(o[2*dp+3], plo[i], vh1[2], vh1[3]);
            }
        }
        __syncthreads();
        if (kt < qt) {
            load_mat(Vh, Vhg + (size_t)(kt + 1) * 128 * HD);
            load_mat(Vl, Vlg + (size_t)(kt + 1) * 128 * HD);
            asm volatile("cp.async.commit_group;" ::: "memory");
        }
    }

    float inv0 = 1.0f / l0, inv1 = 1.0f / l1;
    int b = z >> 4, hh = z & 15;
#pragma unroll
    for (int dt = 0; dt < 16; dt++) {
#pragma unroll
        for (int e = 0; e < 4; e++) {
            int row = wid * 16 + g + ((e >> 1) << 3);
            int q = qt * 128 + row;
            int col = dt * 8 + 2 * tq + (e & 1);
            float v = o[dt][e] * ((e < 2) ? inv0 : inv1);
            size_t off = ((size_t)b * S_LEN + q) * HID + hh * HD + col;
            split_st(v, g_Chi + off, g_Clo + off);
        }
    }
}

// ---------------------------------------------------------------------------
extern "C" void kernel_launch(void* const* d_in, const int* in_sizes, int n_in,
                              void* d_out, int out_size)
{
    (void)in_sizes; (void)n_in; (void)out_size;
    const float* X  = (const float*)d_in[0];
    const float* Wq = (const float*)d_in[3];
    const float* Wk = (const float*)d_in[4];
    const float* Wv = (const float*)d_in[5];
    const float* Wo = (const float*)d_in[6];
    float* out = (float*)d_out;

    cudaFuncSetAttribute(gemm_kernel,
                         cudaFuncAttributeMaxDynamicSharedMemorySize, SMEM_GEMM);
    cudaFuncSetAttribute(flash_kernel,
                         cudaFuncAttributeMaxDynamicSharedMemorySize, SMEM_FLASH);

    conv_kernel<<<24576, 256>>>(X, Wq, Wk, Wv, Wo);
    gemm_kernel<<<1536, 256, SMEM_GEMM>>>(0, nullptr);     // QKV proj
    rope_kernel<<<32768, 256>>>();
    flash_kernel<<<dim3(16, 32), 256, SMEM_FLASH>>>();     // fused attention
    gemm_kernel<<<512, 256, SMEM_GEMM>>>(3, out);          // out proj
}